// round 1
// baseline (speedup 1.0000x reference)
#include <cuda_runtime.h>
#include <math.h>
#include <stdint.h>

// ---------------- problem constants ----------------
#define BATCH 16
#define HDIM  56
#define WDIM  56
#define CH    512
#define CFF   2048
#define NHEAD 16
#define DH    32
#define MWIN  7
#define NTOKW 49          // tokens per window
#define SHIFT 3
#define NTOK  (BATCH*HDIM*WDIM)    // 50176
#define NWIN  (BATCH*(HDIM/MWIN)*(WDIM/MWIN))  // 1024

// ---------------- device scratch (allocation-free) ----------------
__device__ float g_xw  [(size_t)NTOK*CH];     // LN1 + windowed
__device__ float g_qkv [(size_t)NTOK*3*CH];   // qkv projections
__device__ float g_att [(size_t)NTOK*CH];     // attention output (window order)
__device__ float g_proj[(size_t)NTOK*CH];     // proj output (window order)
__device__ float g_x2  [(size_t)NTOK*CH];     // x + attn branch (natural order)
__device__ float g_h2  [(size_t)NTOK*CH];     // LN2 output
__device__ float g_ffn [(size_t)NTOK*CFF];    // FFN hidden

// ---------------- block reduction (256 threads) ----------------
__device__ __forceinline__ void block_reduce_2(float& s, float& sq) {
    __shared__ float sh[16];
    int lane = threadIdx.x & 31, wid = threadIdx.x >> 5;
    #pragma unroll
    for (int o = 16; o > 0; o >>= 1) {
        s  += __shfl_down_sync(0xffffffffu, s,  o);
        sq += __shfl_down_sync(0xffffffffu, sq, o);
    }
    if (lane == 0) { sh[wid] = s; sh[wid + 8] = sq; }
    __syncthreads();
    if (threadIdx.x == 0) {
        float S = 0.f, SQ = 0.f;
        #pragma unroll
        for (int i = 0; i < 8; i++) { S += sh[i]; SQ += sh[i + 8]; }
        sh[0] = S; sh[8] = SQ;
    }
    __syncthreads();
    s = sh[0]; sq = sh[8];
}

// ---------------- kernel 1: LN1 + shift + window partition ----------------
// one block (256 threads) per windowed token; each thread handles 2 channels
__global__ __launch_bounds__(256) void ln1_window_kernel(
    const float* __restrict__ x, const float* __restrict__ g, const float* __restrict__ b,
    float* __restrict__ out)
{
    int t = blockIdx.x;                 // windowed token id: win*49 + tok
    int w = t / NTOKW, tok = t - w * NTOKW;
    int bb = w >> 6;                    // 64 windows per batch
    int wrem = w & 63;
    int wi = wrem >> 3, wj = wrem & 7;  // 8x8 window grid
    int ti = tok / MWIN, tj = tok - ti * MWIN;
    int r = (wi * MWIN + ti + SHIFT) % HDIM;   // roll(-SHIFT): shifted[i] = src[(i+SHIFT)%H]
    int c = (wj * MWIN + tj + SHIFT) % WDIM;
    const float* src = x + ((size_t)bb * (HDIM * WDIM) + r * WDIM + c) * CH;
    int tid = threadIdx.x;
    float v0 = src[tid], v1 = src[tid + 256];
    float s = v0 + v1, sq = v0 * v0 + v1 * v1;
    block_reduce_2(s, sq);
    float mu  = s * (1.0f / CH);
    float var = sq * (1.0f / CH) - mu * mu;
    float inv = rsqrtf(var + 1e-5f);
    float* dst = out + (size_t)t * CH;
    dst[tid]       = (v0 - mu) * inv * g[tid]       + b[tid];
    dst[tid + 256] = (v1 - mu) * inv * g[tid + 256] + b[tid + 256];
}

// ---------------- generic tiled SGEMM with fused epilogue ----------------
// C[M,N] = A[M,K] @ B[K,N] + bias[N]  (EPI=0)
// EPI=1: apply exact GELU after bias
// EPI=2: add residual res[M,N] after bias
// all dims divisible: M%128==0, N%128==0, K%16==0
template<int EPI>
__global__ __launch_bounds__(256) void gemm_kernel(
    const float* __restrict__ A, const float* __restrict__ B,
    const float* __restrict__ bias, const float* __restrict__ res,
    float* __restrict__ Cc, int Mr, int Nc, int K)
{
    constexpr int BM = 128, BN = 128, BK = 16, TM = 8, TN = 8;
    __shared__ float As[BK][BM];
    __shared__ float Bs[BK][BN + 4];
    int bx = blockIdx.x, by = blockIdx.y;
    int tid = threadIdx.x;
    int tr = tid >> 4, tc = tid & 15;
    float acc[TM][TN];
    #pragma unroll
    for (int i = 0; i < TM; i++)
        #pragma unroll
        for (int j = 0; j < TN; j++) acc[i][j] = 0.f;

    const float* Ab = A + (size_t)by * BM * K;
    const float* Bb = B + (size_t)bx * BN;

    for (int k0 = 0; k0 < K; k0 += BK) {
        // A tile: 128x16 = 512 float4 loads; store transposed
        #pragma unroll
        for (int i = 0; i < 2; i++) {
            int f = tid + i * 256;
            int r = f >> 2, cv = f & 3;
            float4 v = *(const float4*)(Ab + (size_t)r * K + k0 + cv * 4);
            As[cv * 4 + 0][r] = v.x;
            As[cv * 4 + 1][r] = v.y;
            As[cv * 4 + 2][r] = v.z;
            As[cv * 4 + 3][r] = v.w;
        }
        // B tile: 16x128 = 512 float4 loads
        #pragma unroll
        for (int i = 0; i < 2; i++) {
            int f = tid + i * 256;
            int r = f >> 5, cv = f & 31;
            float4 v = *(const float4*)(Bb + (size_t)(k0 + r) * Nc + cv * 4);
            *(float4*)(&Bs[r][cv * 4]) = v;
        }
        __syncthreads();
        #pragma unroll
        for (int k = 0; k < BK; k++) {
            float a[TM], bfr[TN];
            #pragma unroll
            for (int i = 0; i < TM; i++) a[i] = As[k][tr * TM + i];
            #pragma unroll
            for (int j = 0; j < TN; j++) bfr[j] = Bs[k][tc * TN + j];
            #pragma unroll
            for (int i = 0; i < TM; i++)
                #pragma unroll
                for (int j = 0; j < TN; j++)
                    acc[i][j] = fmaf(a[i], bfr[j], acc[i][j]);
        }
        __syncthreads();
    }

    #pragma unroll
    for (int i = 0; i < TM; i++) {
        size_t row = (size_t)by * BM + tr * TM + i;
        #pragma unroll
        for (int j = 0; j < TN; j++) {
            int col = bx * BN + tc * TN + j;
            float v = acc[i][j] + bias[col];
            if (EPI == 1) v = 0.5f * v * (1.0f + erff(v * 0.70710678118654752f));
            if (EPI == 2) v += res[row * Nc + col];
            Cc[row * Nc + col] = v;
        }
    }
}

// ---------------- kernel 3: windowed attention ----------------
// one block (128 threads) per (window, head)
__global__ __launch_bounds__(128) void attn_kernel(
    const float* __restrict__ qkv, const float* __restrict__ bias_table,
    float* __restrict__ out)
{
    int win  = blockIdx.x >> 4;
    int head = blockIdx.x & 15;
    __shared__ float q[NTOKW][DH], kk[NTOKW][DH], v[NTOKW][DH];
    __shared__ float sc[NTOKW][NTOKW + 1];
    int tid = threadIdx.x;
    const float scale = 0.17677669529663687f;  // 32^-0.5
    size_t base = (size_t)win * NTOKW * (3 * CH) + head * DH;
    for (int i = tid; i < NTOKW * DH; i += 128) {
        int n = i / DH, d = i - n * DH;
        size_t rb = base + (size_t)n * (3 * CH);
        q[n][d]  = qkv[rb + d];
        kk[n][d] = qkv[rb + CH + d];
        v[n][d]  = qkv[rb + 2 * CH + d];
    }
    __syncthreads();
    for (int i = tid; i < NTOKW * NTOKW; i += 128) {
        int n = i / NTOKW, m = i - n * NTOKW;
        float s = 0.f;
        #pragma unroll
        for (int d = 0; d < DH; d++) s = fmaf(q[n][d], kk[m][d], s);
        int dr = n / MWIN - m / MWIN + (MWIN - 1);
        int dc = n % MWIN - m % MWIN + (MWIN - 1);
        sc[n][m] = s * scale + bias_table[(dr * (2 * MWIN - 1) + dc) * NHEAD + head];
    }
    __syncthreads();
    if (tid < NTOKW) {
        float mx = -1e30f;
        #pragma unroll 7
        for (int m = 0; m < NTOKW; m++) mx = fmaxf(mx, sc[tid][m]);
        float sum = 0.f;
        #pragma unroll 7
        for (int m = 0; m < NTOKW; m++) { float e = expf(sc[tid][m] - mx); sc[tid][m] = e; sum += e; }
        float inv = 1.0f / sum;
        #pragma unroll 7
        for (int m = 0; m < NTOKW; m++) sc[tid][m] *= inv;
    }
    __syncthreads();
    for (int i = tid; i < NTOKW * DH; i += 128) {
        int n = i / DH, d = i - n * DH;
        float s = 0.f;
        #pragma unroll 7
        for (int m = 0; m < NTOKW; m++) s = fmaf(sc[n][m], v[m][d], s);
        out[((size_t)win * NTOKW + n) * CH + head * DH + d] = s;
    }
}

// ---------------- kernel 5: window reverse + roll + residual + LN2 ----------------
// one block per natural-order token
__global__ __launch_bounds__(256) void res_ln2_kernel(
    const float* __restrict__ x, const float* __restrict__ proj,
    const float* __restrict__ g, const float* __restrict__ b,
    float* __restrict__ x2, float* __restrict__ h2)
{
    int t = blockIdx.x;                 // natural token: bb*3136 + r*56 + c
    int bb = t / (HDIM * WDIM);
    int rc = t - bb * (HDIM * WDIM);
    int r = rc / WDIM, c = rc - r * WDIM;
    int rs = (r - SHIFT + HDIM) % HDIM;   // roll(+SHIFT): out[r] = img[(r-SHIFT)%H]
    int cs = (c - SHIFT + WDIM) % WDIM;
    int w   = bb * 64 + (rs / MWIN) * 8 + (cs / MWIN);
    int tok = (rs % MWIN) * MWIN + (cs % MWIN);
    const float* ps = proj + ((size_t)w * NTOKW + tok) * CH;
    const float* xs = x + (size_t)t * CH;
    int tid = threadIdx.x;
    float v0 = xs[tid] + ps[tid];
    float v1 = xs[tid + 256] + ps[tid + 256];
    float* x2p = x2 + (size_t)t * CH;
    x2p[tid] = v0; x2p[tid + 256] = v1;
    float s = v0 + v1, sq = v0 * v0 + v1 * v1;
    block_reduce_2(s, sq);
    float mu  = s * (1.0f / CH);
    float var = sq * (1.0f / CH) - mu * mu;
    float inv = rsqrtf(var + 1e-5f);
    float* dst = h2 + (size_t)t * CH;
    dst[tid]       = (v0 - mu) * inv * g[tid]       + b[tid];
    dst[tid + 256] = (v1 - mu) * inv * g[tid + 256] + b[tid + 256];
}

// ---------------- launcher ----------------
extern "C" void kernel_launch(void* const* d_in, const int* in_sizes, int n_in,
                              void* d_out, int out_size)
{
    const float* x          = (const float*)d_in[0];
    const float* w_qkv      = (const float*)d_in[3];
    const float* b_qkv      = (const float*)d_in[4];
    const float* w_proj     = (const float*)d_in[5];
    const float* b_proj     = (const float*)d_in[6];
    const float* bias_table = (const float*)d_in[7];
    const float* g1         = (const float*)d_in[8];
    const float* be1        = (const float*)d_in[9];
    const float* g2         = (const float*)d_in[10];
    const float* be2        = (const float*)d_in[11];
    const float* w1         = (const float*)d_in[12];
    const float* b1         = (const float*)d_in[13];
    const float* w2         = (const float*)d_in[14];
    const float* b2         = (const float*)d_in[15];
    float* out = (float*)d_out;

    float *p_xw, *p_qkv, *p_att, *p_proj, *p_x2, *p_h2, *p_ffn;
    cudaGetSymbolAddress((void**)&p_xw,   g_xw);
    cudaGetSymbolAddress((void**)&p_qkv,  g_qkv);
    cudaGetSymbolAddress((void**)&p_att,  g_att);
    cudaGetSymbolAddress((void**)&p_proj, g_proj);
    cudaGetSymbolAddress((void**)&p_x2,   g_x2);
    cudaGetSymbolAddress((void**)&p_h2,   g_h2);
    cudaGetSymbolAddress((void**)&p_ffn,  g_ffn);

    // 1. LN1 + shift + window partition
    ln1_window_kernel<<<NTOK, 256>>>(x, g1, be1, p_xw);

    // 2. QKV GEMM: (50176 x 512) @ (512 x 1536) + b
    gemm_kernel<0><<<dim3((3 * CH) / 128, NTOK / 128), 256>>>(
        p_xw, w_qkv, b_qkv, nullptr, p_qkv, NTOK, 3 * CH, CH);

    // 3. windowed attention
    attn_kernel<<<NWIN * NHEAD, 128>>>(p_qkv, bias_table, p_att);

    // 4. proj GEMM: (50176 x 512) @ (512 x 512) + b
    gemm_kernel<0><<<dim3(CH / 128, NTOK / 128), 256>>>(
        p_att, w_proj, b_proj, nullptr, p_proj, NTOK, CH, CH);

    // 5. window reverse + roll + residual + LN2
    res_ln2_kernel<<<NTOK, 256>>>(x, p_proj, g2, be2, p_x2, p_h2);

    // 6. FFN1: (50176 x 512) @ (512 x 2048) + b1, GELU
    gemm_kernel<1><<<dim3(CFF / 128, NTOK / 128), 256>>>(
        p_h2, w1, b1, nullptr, p_ffn, NTOK, CFF, CH);

    // 7. FFN2: (50176 x 2048) @ (2048 x 512) + b2 + residual -> out
    gemm_kernel<2><<<dim3(CH / 128, NTOK / 128), 256>>>(
        p_ffn, w2, b2, p_x2, out, NTOK, CH, CFF);
}

// round 3
// speedup vs baseline: 1.6752x; 1.6752x over previous
#include <cuda_runtime.h>
#include <cuda_bf16.h>
#include <math.h>
#include <stdint.h>

// ---------------- problem constants ----------------
#define BATCH 16
#define HDIM  56
#define WDIM  56
#define CH    512
#define CFF   2048
#define NHEAD 16
#define DH    32
#define MWIN  7
#define NTOKW 49
#define SHIFT 3
#define NTOK  (BATCH*HDIM*WDIM)                  // 50176
#define NWIN  (BATCH*(HDIM/MWIN)*(WDIM/MWIN))    // 1024

typedef __nv_bfloat16 bf16;

// ---------------- device scratch (allocation-free) ----------------
__device__ bf16  g_xw_h [(size_t)NTOK*CH],  g_xw_l [(size_t)NTOK*CH];
__device__ float g_qkv  [(size_t)NTOK*3*CH];
__device__ bf16  g_att_h[(size_t)NTOK*CH],  g_att_l[(size_t)NTOK*CH];
__device__ float g_proj [(size_t)NTOK*CH];
__device__ float g_x2   [(size_t)NTOK*CH];
__device__ bf16  g_h2_h [(size_t)NTOK*CH],  g_h2_l [(size_t)NTOK*CH];
__device__ bf16  g_ffn_h[(size_t)NTOK*CFF], g_ffn_l[(size_t)NTOK*CFF];
// weights transposed to [N,K], bf16 hi/lo
__device__ bf16 g_wqkv_h [(size_t)CH*3*CH], g_wqkv_l [(size_t)CH*3*CH];
__device__ bf16 g_wproj_h[(size_t)CH*CH],   g_wproj_l[(size_t)CH*CH];
__device__ bf16 g_w1_h   [(size_t)CH*CFF],  g_w1_l   [(size_t)CH*CFF];
__device__ bf16 g_w2_h   [(size_t)CFF*CH],  g_w2_l   [(size_t)CFF*CH];

// ---------------- PTX helpers ----------------
__device__ __forceinline__ uint32_t smem_u32(const void* p){
    uint32_t a;
    asm("{ .reg .u64 t; cvta.to.shared.u64 t, %1; cvt.u32.u64 %0, t; }" : "=r"(a) : "l"(p));
    return a;
}
#define CP_ASYNC16(dst, src) \
    asm volatile("cp.async.cg.shared.global [%0], [%1], 16;" :: "r"(dst), "l"(src))
#define CP_COMMIT() asm volatile("cp.async.commit_group;" ::: "memory")
#define CP_WAIT(N)  asm volatile("cp.async.wait_group %0;" :: "n"(N) : "memory")

#define LDSM_X4(r, a) \
    asm volatile("ldmatrix.sync.aligned.m8n8.x4.shared.b16 {%0,%1,%2,%3}, [%4];" \
        : "=r"((r)[0]), "=r"((r)[1]), "=r"((r)[2]), "=r"((r)[3]) : "r"(a))

#define MMA_BF16(d, a, b0, b1) \
    asm volatile("mma.sync.aligned.m16n8k16.row.col.f32.bf16.bf16.f32 " \
        "{%0,%1,%2,%3}, {%4,%5,%6,%7}, {%8,%9}, {%0,%1,%2,%3};" \
        : "+f"((d)[0]), "+f"((d)[1]), "+f"((d)[2]), "+f"((d)[3]) \
        : "r"((a)[0]), "r"((a)[1]), "r"((a)[2]), "r"((a)[3]), "r"(b0), "r"(b1))

// ---------------- HMMA bf16 hi/lo GEMM ----------------
// C[M,N] = A @ B^T + bias ; A: [M,K] bf16 hi/lo, B: [N,K] bf16 hi/lo.
// EPI=0: fp32 out. EPI=1: GELU -> bf16 hi/lo out. EPI=2: +res -> fp32 out.
// grid=(Nc/128, M/128), block=256. smem = 2 stages x 64KB.
#define GSMEM (2*65536)

template<int EPI>
__global__ __launch_bounds__(256, 1) void hmma_gemm(
    const bf16* __restrict__ Agh, const bf16* __restrict__ Agl,
    const bf16* __restrict__ Bgh, const bf16* __restrict__ Bgl,
    const float* __restrict__ bias, const float* __restrict__ res,
    float* __restrict__ Cf, bf16* __restrict__ Ch, bf16* __restrict__ Cl,
    int K, int Nc)
{
    extern __shared__ char smem[];
    const int tid = threadIdx.x;
    const int lane = tid & 31, wid = tid >> 5;
    const int wm = wid & 1, wn = wid >> 1;          // warp tile: 64 x 32

    const bf16* Ahb = Agh + (size_t)blockIdx.y * 128 * K;
    const bf16* Alb = Agl + (size_t)blockIdx.y * 128 * K;
    const bf16* Bhb = Bgh + (size_t)blockIdx.x * 128 * K;
    const bf16* Blb = Bgl + (size_t)blockIdx.x * 128 * K;

    const uint32_t sb = smem_u32(smem);
    const int NK = K >> 6;

    float acc[4][4][4];
    #pragma unroll
    for (int a = 0; a < 4; a++)
        #pragma unroll
        for (int b = 0; b < 4; b++)
            #pragma unroll
            for (int c = 0; c < 4; c++) acc[a][b][c] = 0.f;

    // --- stage loader: 4 tiles (Ah,Al,Bh,Bl) of 128x64 bf16, SW128 rows ---
    const int lr = tid >> 1;                // row 0..127
    const int lc0 = (tid & 1) * 4;          // chunk base (16B chunks, 8 per row)
    auto load_stage = [&](int kb, int s) {
        uint32_t st = sb + (uint32_t)s * 65536u;
        size_t go = (size_t)lr * K + kb * 64;
        #pragma unroll
        for (int i = 0; i < 4; i++) {
            int c = lc0 + i;
            uint32_t off = (uint32_t)(lr * 128 + ((c ^ (lr & 7)) * 16));
            CP_ASYNC16(st +          off, Ahb + go + c * 8);
            CP_ASYNC16(st + 16384u + off, Alb + go + c * 8);
            CP_ASYNC16(st + 32768u + off, Bhb + go + c * 8);
            CP_ASYNC16(st + 49152u + off, Blb + go + c * 8);
        }
        CP_COMMIT();
    };

    auto compute_stage = [&](int s) {
        uint32_t st = sb + (uint32_t)s * 65536u;
        #pragma unroll
        for (int kk = 0; kk < 4; kk++) {
            uint32_t ah[4][4], al[4][4];
            #pragma unroll
            for (int mt = 0; mt < 4; mt++) {
                int row = wm * 64 + mt * 16 + (lane & 15);
                int ch  = kk * 2 + (lane >> 4);
                uint32_t off = (uint32_t)(row * 128 + ((ch ^ (row & 7)) * 16));
                LDSM_X4(ah[mt], st + off);
                LDSM_X4(al[mt], st + 16384u + off);
            }
            uint32_t bh[2][4], bl[2][4];
            #pragma unroll
            for (int np = 0; np < 2; np++) {
                int row = wn * 32 + np * 16 + (lane & 15);
                int ch  = kk * 2 + (lane >> 4);
                uint32_t off = (uint32_t)(row * 128 + ((ch ^ (row & 7)) * 16));
                LDSM_X4(bh[np], st + 32768u + off);
                LDSM_X4(bl[np], st + 49152u + off);
            }
            #pragma unroll
            for (int mt = 0; mt < 4; mt++)
                #pragma unroll
                for (int nt = 0; nt < 4; nt++) {
                    int np = nt >> 1, se = nt & 1;
                    MMA_BF16(acc[mt][nt], ah[mt], bh[np][se], bh[np][se + 2]);
                    MMA_BF16(acc[mt][nt], ah[mt], bl[np][se], bl[np][se + 2]);
                    MMA_BF16(acc[mt][nt], al[mt], bh[np][se], bh[np][se + 2]);
                }
        }
    };

    load_stage(0, 0);
    for (int kb = 0; kb < NK; kb++) {
        int cur = kb & 1;
        if (kb + 1 < NK) {
            load_stage(kb + 1, cur ^ 1);
            CP_WAIT(1);
        } else {
            CP_WAIT(0);
        }
        __syncthreads();
        compute_stage(cur);
        __syncthreads();
    }

    // --- epilogue: registers -> gmem ---
    int row0 = blockIdx.y * 128 + wm * 64;
    int col0 = blockIdx.x * 128 + wn * 32;
    #pragma unroll
    for (int mt = 0; mt < 4; mt++) {
        #pragma unroll
        for (int nt = 0; nt < 4; nt++) {
            int c = col0 + nt * 8 + (lane & 3) * 2;
            float b0 = bias[c], b1 = bias[c + 1];
            #pragma unroll
            for (int h = 0; h < 2; h++) {
                int r = row0 + mt * 16 + (lane >> 2) + h * 8;
                float v0 = acc[mt][nt][h * 2]     + b0;
                float v1 = acc[mt][nt][h * 2 + 1] + b1;
                size_t o = (size_t)r * Nc + c;
                if (EPI == 1) {
                    v0 = 0.5f * v0 * (1.0f + erff(v0 * 0.70710678118654752f));
                    v1 = 0.5f * v1 * (1.0f + erff(v1 * 0.70710678118654752f));
                    bf16 h0 = __float2bfloat16(v0), h1 = __float2bfloat16(v1);
                    bf16 l0 = __float2bfloat16(v0 - __bfloat162float(h0));
                    bf16 l1 = __float2bfloat16(v1 - __bfloat162float(h1));
                    *(__nv_bfloat162*)(Ch + o) = __nv_bfloat162(h0, h1);
                    *(__nv_bfloat162*)(Cl + o) = __nv_bfloat162(l0, l1);
                } else {
                    if (EPI == 2) {
                        float2 rv = *(const float2*)(res + o);
                        v0 += rv.x; v1 += rv.y;
                    }
                    *(float2*)(Cf + o) = make_float2(v0, v1);
                }
            }
        }
    }
}

// ---------------- weight prep: [K,N] fp32 -> [N,K] bf16 hi/lo ----------------
__global__ __launch_bounds__(256) void prep_w(
    const float* __restrict__ W, bf16* __restrict__ Wh, bf16* __restrict__ Wl,
    int K, int N)
{
    int idx = blockIdx.x * 256 + threadIdx.x;
    if (idx >= K * N) return;
    int k = idx / N, n = idx - k * N;
    float w = W[idx];
    bf16 h = __float2bfloat16(w);
    Wh[(size_t)n * K + k] = h;
    Wl[(size_t)n * K + k] = __float2bfloat16(w - __bfloat162float(h));
}

// ---------------- block reduction (256 threads) ----------------
__device__ __forceinline__ void block_reduce_2(float& s, float& sq) {
    __shared__ float sh[16];
    int lane = threadIdx.x & 31, wid = threadIdx.x >> 5;
    #pragma unroll
    for (int o = 16; o > 0; o >>= 1) {
        s  += __shfl_down_sync(0xffffffffu, s,  o);
        sq += __shfl_down_sync(0xffffffffu, sq, o);
    }
    if (lane == 0) { sh[wid] = s; sh[wid + 8] = sq; }
    __syncthreads();
    if (threadIdx.x == 0) {
        float S = 0.f, SQ = 0.f;
        #pragma unroll
        for (int i = 0; i < 8; i++) { S += sh[i]; SQ += sh[i + 8]; }
        sh[0] = S; sh[8] = SQ;
    }
    __syncthreads();
    s = sh[0]; sq = sh[8];
}

__device__ __forceinline__ void split_store(bf16* ph, bf16* pl, size_t o, float v) {
    bf16 h = __float2bfloat16(v);
    ph[o] = h;
    pl[o] = __float2bfloat16(v - __bfloat162float(h));
}

// ---------------- LN1 + shift + window partition -> bf16 hi/lo ----------------
__global__ __launch_bounds__(256) void ln1_window_kernel(
    const float* __restrict__ x, const float* __restrict__ g, const float* __restrict__ b,
    bf16* __restrict__ outh, bf16* __restrict__ outl)
{
    int t = blockIdx.x;
    int w = t / NTOKW, tok = t - w * NTOKW;
    int bb = w >> 6, wrem = w & 63;
    int wi = wrem >> 3, wj = wrem & 7;
    int ti = tok / MWIN, tj = tok - ti * MWIN;
    int r = (wi * MWIN + ti + SHIFT) % HDIM;
    int c = (wj * MWIN + tj + SHIFT) % WDIM;
    const float* src = x + ((size_t)bb * (HDIM * WDIM) + r * WDIM + c) * CH;
    int tid = threadIdx.x;
    float v0 = src[tid], v1 = src[tid + 256];
    float s = v0 + v1, sq = v0 * v0 + v1 * v1;
    block_reduce_2(s, sq);
    float mu  = s * (1.0f / CH);
    float var = sq * (1.0f / CH) - mu * mu;
    float inv = rsqrtf(var + 1e-5f);
    size_t base = (size_t)t * CH;
    split_store(outh, outl, base + tid,       (v0 - mu) * inv * g[tid]       + b[tid]);
    split_store(outh, outl, base + tid + 256, (v1 - mu) * inv * g[tid + 256] + b[tid + 256]);
}

// ---------------- windowed attention ----------------
__global__ __launch_bounds__(128) void attn_kernel(
    const float* __restrict__ qkv, const float* __restrict__ bias_table,
    bf16* __restrict__ outh, bf16* __restrict__ outl)
{
    int win  = blockIdx.x >> 4;
    int head = blockIdx.x & 15;
    __shared__ float q[NTOKW][DH], kk[NTOKW][DH], v[NTOKW][DH];
    __shared__ float sc[NTOKW][NTOKW + 1];
    int tid = threadIdx.x;
    const float scale = 0.17677669529663687f;
    size_t base = (size_t)win * NTOKW * (3 * CH) + head * DH;
    for (int i = tid; i < NTOKW * DH; i += 128) {
        int n = i / DH, d = i - n * DH;
        size_t rb = base + (size_t)n * (3 * CH);
        q[n][d]  = qkv[rb + d];
        kk[n][d] = qkv[rb + CH + d];
        v[n][d]  = qkv[rb + 2 * CH + d];
    }
    __syncthreads();
    for (int i = tid; i < NTOKW * NTOKW; i += 128) {
        int n = i / NTOKW, m = i - n * NTOKW;
        float s = 0.f;
        #pragma unroll
        for (int d = 0; d < DH; d++) s = fmaf(q[n][d], kk[m][d], s);
        int dr = n / MWIN - m / MWIN + (MWIN - 1);
        int dc = n % MWIN - m % MWIN + (MWIN - 1);
        sc[n][m] = s * scale + bias_table[(dr * (2 * MWIN - 1) + dc) * NHEAD + head];
    }
    __syncthreads();
    if (tid < NTOKW) {
        float mx = -1e30f;
        #pragma unroll 7
        for (int m = 0; m < NTOKW; m++) mx = fmaxf(mx, sc[tid][m]);
        float sum = 0.f;
        #pragma unroll 7
        for (int m = 0; m < NTOKW; m++) { float e = expf(sc[tid][m] - mx); sc[tid][m] = e; sum += e; }
        float inv = 1.0f / sum;
        #pragma unroll 7
        for (int m = 0; m < NTOKW; m++) sc[tid][m] *= inv;
    }
    __syncthreads();
    for (int i = tid; i < NTOKW * DH; i += 128) {
        int n = i / DH, d = i - n * DH;
        float s = 0.f;
        #pragma unroll 7
        for (int m = 0; m < NTOKW; m++) s = fmaf(sc[n][m], v[m][d], s);
        split_store(outh, outl, ((size_t)win * NTOKW + n) * CH + head * DH + d, s);
    }
}

// ---------------- window reverse + roll + residual + LN2 ----------------
__global__ __launch_bounds__(256) void res_ln2_kernel(
    const float* __restrict__ x, const float* __restrict__ proj,
    const float* __restrict__ g, const float* __restrict__ b,
    float* __restrict__ x2, bf16* __restrict__ h2h, bf16* __restrict__ h2l)
{
    int t = blockIdx.x;
    int bb = t / (HDIM * WDIM);
    int rc = t - bb * (HDIM * WDIM);
    int r = rc / WDIM, c = rc - r * WDIM;
    int rs = (r - SHIFT + HDIM) % HDIM;
    int cs = (c - SHIFT + WDIM) % WDIM;
    int w   = bb * 64 + (rs / MWIN) * 8 + (cs / MWIN);
    int tok = (rs % MWIN) * MWIN + (cs % MWIN);
    const float* ps = proj + ((size_t)w * NTOKW + tok) * CH;
    const float* xs = x + (size_t)t * CH;
    int tid = threadIdx.x;
    float v0 = xs[tid] + ps[tid];
    float v1 = xs[tid + 256] + ps[tid + 256];
    float* x2p = x2 + (size_t)t * CH;
    x2p[tid] = v0; x2p[tid + 256] = v1;
    float s = v0 + v1, sq = v0 * v0 + v1 * v1;
    block_reduce_2(s, sq);
    float mu  = s * (1.0f / CH);
    float var = sq * (1.0f / CH) - mu * mu;
    float inv = rsqrtf(var + 1e-5f);
    size_t base = (size_t)t * CH;
    split_store(h2h, h2l, base + tid,       (v0 - mu) * inv * g[tid]       + b[tid]);
    split_store(h2h, h2l, base + tid + 256, (v1 - mu) * inv * g[tid + 256] + b[tid + 256]);
}

// ---------------- launcher ----------------
extern "C" void kernel_launch(void* const* d_in, const int* in_sizes, int n_in,
                              void* d_out, int out_size)
{
    const float* x          = (const float*)d_in[0];
    const float* w_qkv      = (const float*)d_in[3];
    const float* b_qkv      = (const float*)d_in[4];
    const float* w_proj     = (const float*)d_in[5];
    const float* b_proj     = (const float*)d_in[6];
    const float* bias_table = (const float*)d_in[7];
    const float* g1         = (const float*)d_in[8];
    const float* be1        = (const float*)d_in[9];
    const float* g2         = (const float*)d_in[10];
    const float* be2        = (const float*)d_in[11];
    const float* w1         = (const float*)d_in[12];
    const float* b1         = (const float*)d_in[13];
    const float* w2         = (const float*)d_in[14];
    const float* b2         = (const float*)d_in[15];
    float* out = (float*)d_out;

    bf16 *p_xw_h, *p_xw_l, *p_att_h, *p_att_l, *p_h2_h, *p_h2_l, *p_ffn_h, *p_ffn_l;
    float *p_qkv, *p_proj, *p_x2;
    bf16 *p_wqkv_h, *p_wqkv_l, *p_wproj_h, *p_wproj_l, *p_w1_h, *p_w1_l, *p_w2_h, *p_w2_l;
    cudaGetSymbolAddress((void**)&p_xw_h,  g_xw_h);
    cudaGetSymbolAddress((void**)&p_xw_l,  g_xw_l);
    cudaGetSymbolAddress((void**)&p_qkv,   g_qkv);
    cudaGetSymbolAddress((void**)&p_att_h, g_att_h);
    cudaGetSymbolAddress((void**)&p_att_l, g_att_l);
    cudaGetSymbolAddress((void**)&p_proj,  g_proj);
    cudaGetSymbolAddress((void**)&p_x2,    g_x2);
    cudaGetSymbolAddress((void**)&p_h2_h,  g_h2_h);
    cudaGetSymbolAddress((void**)&p_h2_l,  g_h2_l);
    cudaGetSymbolAddress((void**)&p_ffn_h, g_ffn_h);
    cudaGetSymbolAddress((void**)&p_ffn_l, g_ffn_l);
    cudaGetSymbolAddress((void**)&p_wqkv_h,  g_wqkv_h);
    cudaGetSymbolAddress((void**)&p_wqkv_l,  g_wqkv_l);
    cudaGetSymbolAddress((void**)&p_wproj_h, g_wproj_h);
    cudaGetSymbolAddress((void**)&p_wproj_l, g_wproj_l);
    cudaGetSymbolAddress((void**)&p_w1_h,    g_w1_h);
    cudaGetSymbolAddress((void**)&p_w1_l,    g_w1_l);
    cudaGetSymbolAddress((void**)&p_w2_h,    g_w2_h);
    cudaGetSymbolAddress((void**)&p_w2_l,    g_w2_l);

    cudaFuncSetAttribute(hmma_gemm<0>, cudaFuncAttributeMaxDynamicSharedMemorySize, GSMEM);
    cudaFuncSetAttribute(hmma_gemm<1>, cudaFuncAttributeMaxDynamicSharedMemorySize, GSMEM);
    cudaFuncSetAttribute(hmma_gemm<2>, cudaFuncAttributeMaxDynamicSharedMemorySize, GSMEM);

    // weight prep (transpose + bf16 hi/lo split)
    prep_w<<<(CH*3*CH + 255)/256, 256>>>(w_qkv, p_wqkv_h, p_wqkv_l, CH, 3*CH);
    prep_w<<<(CH*CH   + 255)/256, 256>>>(w_proj, p_wproj_h, p_wproj_l, CH, CH);
    prep_w<<<(CH*CFF  + 255)/256, 256>>>(w1, p_w1_h, p_w1_l, CH, CFF);
    prep_w<<<(CFF*CH  + 255)/256, 256>>>(w2, p_w2_h, p_w2_l, CFF, CH);

    // 1. LN1 + shift + window partition -> bf16 hi/lo
    ln1_window_kernel<<<NTOK, 256>>>(x, g1, be1, p_xw_h, p_xw_l);

    // 2. QKV GEMM
    hmma_gemm<0><<<dim3((3*CH)/128, NTOK/128), 256, GSMEM>>>(
        p_xw_h, p_xw_l, p_wqkv_h, p_wqkv_l, b_qkv, nullptr,
        p_qkv, nullptr, nullptr, CH, 3*CH);

    // 3. windowed attention -> bf16 hi/lo
    attn_kernel<<<NWIN * NHEAD, 128>>>(p_qkv, bias_table, p_att_h, p_att_l);

    // 4. proj GEMM
    hmma_gemm<0><<<dim3(CH/128, NTOK/128), 256, GSMEM>>>(
        p_att_h, p_att_l, p_wproj_h, p_wproj_l, b_proj, nullptr,
        p_proj, nullptr, nullptr, CH, CH);

    // 5. window reverse + roll + residual + LN2 -> x2 fp32 + h2 bf16 hi/lo
    res_ln2_kernel<<<NTOK, 256>>>(x, p_proj, g2, be2, p_x2, p_h2_h, p_h2_l);

    // 6. FFN1 + GELU -> bf16 hi/lo
    hmma_gemm<1><<<dim3(CFF/128, NTOK/128), 256, GSMEM>>>(
        p_h2_h, p_h2_l, p_w1_h, p_w1_l, b1, nullptr,
        nullptr, p_ffn_h, p_ffn_l, CH, CFF);

    // 7. FFN2 + residual -> out
    hmma_gemm<2><<<dim3(CH/128, NTOK/128), 256, GSMEM>>>(
        p_ffn_h, p_ffn_l, p_w2_h, p_w2_l, b2, p_x2,
        out, nullptr, nullptr, CFF, CH);
}

// round 5
// speedup vs baseline: 1.8662x; 1.1140x over previous
#include <cuda_runtime.h>
#include <cuda_bf16.h>
#include <math.h>
#include <stdint.h>

// ---------------- problem constants ----------------
#define BATCH 16
#define HDIM  56
#define WDIM  56
#define CH    512
#define CFF   2048
#define NHEAD 16
#define DH    32
#define MWIN  7
#define NTOKW 49
#define SHIFT 3
#define NTOK  (BATCH*HDIM*WDIM)                  // 50176
#define NWIN  (BATCH*(HDIM/MWIN)*(WDIM/MWIN))    // 1024

typedef __nv_bfloat16 bf16;

// ---------------- device scratch (allocation-free) ----------------
__device__ bf16  g_xw_h [(size_t)NTOK*CH],  g_xw_l [(size_t)NTOK*CH];
__device__ float g_qkv  [(size_t)NTOK*3*CH];
__device__ bf16  g_att_h[(size_t)NTOK*CH],  g_att_l[(size_t)NTOK*CH];
__device__ float g_proj [(size_t)NTOK*CH];
__device__ float g_x2   [(size_t)NTOK*CH];
__device__ bf16  g_h2_h [(size_t)NTOK*CH],  g_h2_l [(size_t)NTOK*CH];
__device__ bf16  g_ffn_h[(size_t)NTOK*CFF], g_ffn_l[(size_t)NTOK*CFF];
// weights transposed to [N,K], bf16 hi/lo
__device__ bf16 g_wqkv_h [(size_t)CH*3*CH], g_wqkv_l [(size_t)CH*3*CH];
__device__ bf16 g_wproj_h[(size_t)CH*CH],   g_wproj_l[(size_t)CH*CH];
__device__ bf16 g_w1_h   [(size_t)CH*CFF],  g_w1_l   [(size_t)CH*CFF];
__device__ bf16 g_w2_h   [(size_t)CFF*CH],  g_w2_l   [(size_t)CFF*CH];

// ---------------- PTX helpers ----------------
__device__ __forceinline__ uint32_t smem_u32(const void* p){
    uint32_t a;
    asm("{ .reg .u64 t; cvta.to.shared.u64 t, %1; cvt.u32.u64 %0, t; }" : "=r"(a) : "l"(p));
    return a;
}
#define CP_ASYNC16(dst, src) \
    asm volatile("cp.async.cg.shared.global [%0], [%1], 16;" :: "r"(dst), "l"(src))
#define CP_COMMIT() asm volatile("cp.async.commit_group;" ::: "memory")
#define CP_WAIT(N)  asm volatile("cp.async.wait_group %0;" :: "n"(N) : "memory")

#define LDSM_X4(r, a) \
    asm volatile("ldmatrix.sync.aligned.m8n8.x4.shared.b16 {%0,%1,%2,%3}, [%4];" \
        : "=r"((r)[0]), "=r"((r)[1]), "=r"((r)[2]), "=r"((r)[3]) : "r"(a))

#define MMA_BF16(d, a, b0, b1) \
    asm volatile("mma.sync.aligned.m16n8k16.row.col.f32.bf16.bf16.f32 " \
        "{%0,%1,%2,%3}, {%4,%5,%6,%7}, {%8,%9}, {%0,%1,%2,%3};" \
        : "+f"((d)[0]), "+f"((d)[1]), "+f"((d)[2]), "+f"((d)[3]) \
        : "r"((a)[0]), "r"((a)[1]), "r"((a)[2]), "r"((a)[3]), "r"(b0), "r"(b1))

// ---------------- HMMA bf16 hi/lo GEMM ----------------
// C[M,N] = A @ B^T + bias ; A: [M,K] bf16 hi/lo, B: [N,K] bf16 hi/lo.
// CTA tile 128x128, BK=32. smem rows padded to 80B -> conflict-free ldmatrix
// (bank-quad = (5r + c) mod 8 is a permutation over 8 rows).
// Stage = 4 tiles x 128 rows x 80B = 40KB; 2 stages = 80KB -> 2 CTAs/SM.
#define TILEB  10240
#define STAGEB 40960
#define GSMEM  (2*STAGEB)

template<int EPI>
__global__ __launch_bounds__(256, 2) void hmma_gemm(
    const bf16* __restrict__ Agh, const bf16* __restrict__ Agl,
    const bf16* __restrict__ Bgh, const bf16* __restrict__ Bgl,
    const float* __restrict__ bias, const float* __restrict__ res,
    float* __restrict__ Cf, bf16* __restrict__ Ch, bf16* __restrict__ Cl,
    int K, int Nc)
{
    extern __shared__ char smem[];
    const int tid = threadIdx.x;
    const int lane = tid & 31, wid = tid >> 5;
    const int wm = wid & 1, wn = wid >> 1;          // warp tile: 64 x 32

    const bf16* Ahb = Agh + (size_t)blockIdx.y * 128 * K;
    const bf16* Alb = Agl + (size_t)blockIdx.y * 128 * K;
    const bf16* Bhb = Bgh + (size_t)blockIdx.x * 128 * K;
    const bf16* Blb = Bgl + (size_t)blockIdx.x * 128 * K;

    const uint32_t sb = smem_u32(smem);
    const int NK = K >> 5;

    float acc[4][4][4];
    #pragma unroll
    for (int a = 0; a < 4; a++)
        #pragma unroll
        for (int b = 0; b < 4; b++)
            #pragma unroll
            for (int c = 0; c < 4; c++) acc[a][b][c] = 0.f;

    const int lr0 = tid >> 2;          // 0..63
    const int lc  = tid & 3;           // 16B chunk 0..3
    auto load_stage = [&](int kb, int s) {
        uint32_t st = sb + (uint32_t)s * STAGEB;
        const bf16* bases[4] = {Ahb, Alb, Bhb, Blb};
        #pragma unroll
        for (int i = 0; i < 8; i++) {
            const int t = i >> 1;
            int r = (i & 1) * 64 + lr0;
            const bf16* src = bases[t] + (size_t)r * K + kb * 32 + lc * 8;
            uint32_t dst = st + (uint32_t)(t * TILEB + r * 80 + lc * 16);
            CP_ASYNC16(dst, src);
        }
        CP_COMMIT();
    };

    auto compute_stage = [&](int s) {
        uint32_t st = sb + (uint32_t)s * STAGEB;
        #pragma unroll
        for (int kk = 0; kk < 2; kk++) {
            const int ch = kk * 2 + (lane >> 4);
            uint32_t bh[2][4], bl[2][4];
            #pragma unroll
            for (int np = 0; np < 2; np++) {
                int row = wn * 32 + np * 16 + (lane & 15);
                uint32_t off = (uint32_t)(row * 80 + ch * 16);
                LDSM_X4(bh[np], st + 2u * TILEB + off);
                LDSM_X4(bl[np], st + 3u * TILEB + off);
            }
            #pragma unroll
            for (int mt = 0; mt < 4; mt++) {
                int row = wm * 64 + mt * 16 + (lane & 15);
                uint32_t off = (uint32_t)(row * 80 + ch * 16);
                uint32_t ah[4], al[4];
                LDSM_X4(ah, st + off);
                LDSM_X4(al, st + 1u * TILEB + off);
                #pragma unroll
                for (int nt = 0; nt < 4; nt++) {
                    int np = nt >> 1, se = nt & 1;
                    MMA_BF16(acc[mt][nt], ah, bh[np][se], bh[np][se + 2]);
                    MMA_BF16(acc[mt][nt], ah, bl[np][se], bl[np][se + 2]);
                    MMA_BF16(acc[mt][nt], al, bh[np][se], bh[np][se + 2]);
                }
            }
        }
    };

    load_stage(0, 0);
    for (int kb = 0; kb < NK; kb++) {
        int cur = kb & 1;
        if (kb + 1 < NK) {
            load_stage(kb + 1, cur ^ 1);
            CP_WAIT(1);
        } else {
            CP_WAIT(0);
        }
        __syncthreads();
        compute_stage(cur);
        __syncthreads();
    }

    // --- epilogue: registers -> gmem ---
    int row0 = blockIdx.y * 128 + wm * 64;
    int col0 = blockIdx.x * 128 + wn * 32;
    #pragma unroll
    for (int mt = 0; mt < 4; mt++) {
        #pragma unroll
        for (int nt = 0; nt < 4; nt++) {
            int c = col0 + nt * 8 + (lane & 3) * 2;
            float b0 = bias[c], b1 = bias[c + 1];
            #pragma unroll
            for (int h = 0; h < 2; h++) {
                int r = row0 + mt * 16 + (lane >> 2) + h * 8;
                float v0 = acc[mt][nt][h * 2]     + b0;
                float v1 = acc[mt][nt][h * 2 + 1] + b1;
                size_t o = (size_t)r * Nc + c;
                if (EPI == 1) {
                    v0 = 0.5f * v0 * (1.0f + erff(v0 * 0.70710678118654752f));
                    v1 = 0.5f * v1 * (1.0f + erff(v1 * 0.70710678118654752f));
                    bf16 h0 = __float2bfloat16(v0), h1 = __float2bfloat16(v1);
                    bf16 l0 = __float2bfloat16(v0 - __bfloat162float(h0));
                    bf16 l1 = __float2bfloat16(v1 - __bfloat162float(h1));
                    *(__nv_bfloat162*)(Ch + o) = __nv_bfloat162(h0, h1);
                    *(__nv_bfloat162*)(Cl + o) = __nv_bfloat162(l0, l1);
                } else {
                    if (EPI == 2) {
                        float2 rv = *(const float2*)(res + o);
                        v0 += rv.x; v1 += rv.y;
                    }
                    *(float2*)(Cf + o) = make_float2(v0, v1);
                }
            }
        }
    }
}

// ---------------- weight prep: [K,N] fp32 -> [N,K] bf16 hi/lo (tiled transpose) ----------------
__global__ __launch_bounds__(256) void prep_w(
    const float* __restrict__ W, bf16* __restrict__ Wh, bf16* __restrict__ Wl,
    int K, int N)
{
    __shared__ float tile[32][33];
    int nb = blockIdx.x * 32, kb = blockIdx.y * 32;
    int tx = threadIdx.x & 31, ty = threadIdx.x >> 5;  // 32 x 8
    #pragma unroll
    for (int j = 0; j < 32; j += 8)
        tile[ty + j][tx] = W[(size_t)(kb + ty + j) * N + nb + tx];
    __syncthreads();
    #pragma unroll
    for (int j = 0; j < 32; j += 8) {
        float w = tile[tx][ty + j];
        bf16 h = __float2bfloat16(w);
        size_t o = (size_t)(nb + ty + j) * K + kb + tx;
        Wh[o] = h;
        Wl[o] = __float2bfloat16(w - __bfloat162float(h));
    }
}

// ---------------- block reduction (256 threads) ----------------
__device__ __forceinline__ void block_reduce_2(float& s, float& sq) {
    __shared__ float sh[16];
    int lane = threadIdx.x & 31, wid = threadIdx.x >> 5;
    #pragma unroll
    for (int o = 16; o > 0; o >>= 1) {
        s  += __shfl_down_sync(0xffffffffu, s,  o);
        sq += __shfl_down_sync(0xffffffffu, sq, o);
    }
    if (lane == 0) { sh[wid] = s; sh[wid + 8] = sq; }
    __syncthreads();
    if (threadIdx.x == 0) {
        float S = 0.f, SQ = 0.f;
        #pragma unroll
        for (int i = 0; i < 8; i++) { S += sh[i]; SQ += sh[i + 8]; }
        sh[0] = S; sh[8] = SQ;
    }
    __syncthreads();
    s = sh[0]; sq = sh[8];
}

__device__ __forceinline__ void split_store(bf16* ph, bf16* pl, size_t o, float v) {
    bf16 h = __float2bfloat16(v);
    ph[o] = h;
    pl[o] = __float2bfloat16(v - __bfloat162float(h));
}

// ---------------- LN1 + shift + window partition -> bf16 hi/lo ----------------
__global__ __launch_bounds__(256) void ln1_window_kernel(
    const float* __restrict__ x, const float* __restrict__ g, const float* __restrict__ b,
    bf16* __restrict__ outh, bf16* __restrict__ outl)
{
    int t = blockIdx.x;
    int w = t / NTOKW, tok = t - w * NTOKW;
    int bb = w >> 6, wrem = w & 63;
    int wi = wrem >> 3, wj = wrem & 7;
    int ti = tok / MWIN, tj = tok - ti * MWIN;
    int r = (wi * MWIN + ti + SHIFT) % HDIM;
    int c = (wj * MWIN + tj + SHIFT) % WDIM;
    const float* src = x + ((size_t)bb * (HDIM * WDIM) + r * WDIM + c) * CH;
    int tid = threadIdx.x;
    float v0 = src[tid], v1 = src[tid + 256];
    float s = v0 + v1, sq = v0 * v0 + v1 * v1;
    block_reduce_2(s, sq);
    float mu  = s * (1.0f / CH);
    float var = sq * (1.0f / CH) - mu * mu;
    float inv = rsqrtf(var + 1e-5f);
    size_t base = (size_t)t * CH;
    split_store(outh, outl, base + tid,       (v0 - mu) * inv * g[tid]       + b[tid]);
    split_store(outh, outl, base + tid + 256, (v1 - mu) * inv * g[tid + 256] + b[tid + 256]);
}

// ---------------- windowed attention ----------------
__global__ __launch_bounds__(128) void attn_kernel(
    const float* __restrict__ qkv, const float* __restrict__ bias_table,
    bf16* __restrict__ outh, bf16* __restrict__ outl)
{
    int win  = blockIdx.x >> 4;
    int head = blockIdx.x & 15;
    __shared__ float q[NTOKW][DH], kk[NTOKW][DH], v[NTOKW][DH];
    __shared__ float sc[NTOKW][NTOKW + 1];
    int tid = threadIdx.x;
    const float scale = 0.17677669529663687f;
    size_t base = (size_t)win * NTOKW * (3 * CH) + head * DH;
    for (int i = tid; i < NTOKW * DH; i += 128) {
        int n = i / DH, d = i - n * DH;
        size_t rb = base + (size_t)n * (3 * CH);
        q[n][d]  = qkv[rb + d];
        kk[n][d] = qkv[rb + CH + d];
        v[n][d]  = qkv[rb + 2 * CH + d];
    }
    __syncthreads();
    for (int i = tid; i < NTOKW * NTOKW; i += 128) {
        int n = i / NTOKW, m = i - n * NTOKW;
        float s = 0.f;
        #pragma unroll
        for (int d = 0; d < DH; d++) s = fmaf(q[n][d], kk[m][d], s);
        int dr = n / MWIN - m / MWIN + (MWIN - 1);
        int dc = n % MWIN - m % MWIN + (MWIN - 1);
        sc[n][m] = s * scale + bias_table[(dr * (2 * MWIN - 1) + dc) * NHEAD + head];
    }
    __syncthreads();
    if (tid < NTOKW) {
        float mx = -1e30f;
        #pragma unroll 7
        for (int m = 0; m < NTOKW; m++) mx = fmaxf(mx, sc[tid][m]);
        float sum = 0.f;
        #pragma unroll 7
        for (int m = 0; m < NTOKW; m++) { float e = expf(sc[tid][m] - mx); sc[tid][m] = e; sum += e; }
        float inv = 1.0f / sum;
        #pragma unroll 7
        for (int m = 0; m < NTOKW; m++) sc[tid][m] *= inv;
    }
    __syncthreads();
    for (int i = tid; i < NTOKW * DH; i += 128) {
        int n = i / DH, d = i - n * DH;
        float s = 0.f;
        #pragma unroll 7
        for (int m = 0; m < NTOKW; m++) s = fmaf(sc[n][m], v[m][d], s);
        split_store(outh, outl, ((size_t)win * NTOKW + n) * CH + head * DH + d, s);
    }
}

// ---------------- window reverse + roll + residual + LN2 ----------------
__global__ __launch_bounds__(256) void res_ln2_kernel(
    const float* __restrict__ x, const float* __restrict__ proj,
    const float* __restrict__ g, const float* __restrict__ b,
    float* __restrict__ x2, bf16* __restrict__ h2h, bf16* __restrict__ h2l)
{
    int t = blockIdx.x;
    int bb = t / (HDIM * WDIM);
    int rc = t - bb * (HDIM * WDIM);
    int r = rc / WDIM, c = rc - r * WDIM;
    int rs = (r - SHIFT + HDIM) % HDIM;
    int cs = (c - SHIFT + WDIM) % WDIM;
    int w   = bb * 64 + (rs / MWIN) * 8 + (cs / MWIN);
    int tok = (rs % MWIN) * MWIN + (cs % MWIN);
    const float* ps = proj + ((size_t)w * NTOKW + tok) * CH;
    const float* xs = x + (size_t)t * CH;
    int tid = threadIdx.x;
    float v0 = xs[tid] + ps[tid];
    float v1 = xs[tid + 256] + ps[tid + 256];
    float* x2p = x2 + (size_t)t * CH;
    x2p[tid] = v0; x2p[tid + 256] = v1;
    float s = v0 + v1, sq = v0 * v0 + v1 * v1;
    block_reduce_2(s, sq);
    float mu  = s * (1.0f / CH);
    float var = sq * (1.0f / CH) - mu * mu;
    float inv = rsqrtf(var + 1e-5f);
    size_t base = (size_t)t * CH;
    split_store(h2h, h2l, base + tid,       (v0 - mu) * inv * g[tid]       + b[tid]);
    split_store(h2h, h2l, base + tid + 256, (v1 - mu) * inv * g[tid + 256] + b[tid + 256]);
}

// ---------------- launcher ----------------
extern "C" void kernel_launch(void* const* d_in, const int* in_sizes, int n_in,
                              void* d_out, int out_size)
{
    const float* x          = (const float*)d_in[0];
    const float* w_qkv      = (const float*)d_in[3];
    const float* b_qkv      = (const float*)d_in[4];
    const float* w_proj     = (const float*)d_in[5];
    const float* b_proj     = (const float*)d_in[6];
    const float* bias_table = (const float*)d_in[7];
    const float* g1         = (const float*)d_in[8];
    const float* be1        = (const float*)d_in[9];
    const float* g2         = (const float*)d_in[10];
    const float* be2        = (const float*)d_in[11];
    const float* w1         = (const float*)d_in[12];
    const float* b1         = (const float*)d_in[13];
    const float* w2         = (const float*)d_in[14];
    const float* b2         = (const float*)d_in[15];
    float* out = (float*)d_out;

    bf16 *p_xw_h, *p_xw_l, *p_att_h, *p_att_l, *p_h2_h, *p_h2_l, *p_ffn_h, *p_ffn_l;
    float *p_qkv, *p_proj, *p_x2;
    bf16 *p_wqkv_h, *p_wqkv_l, *p_wproj_h, *p_wproj_l, *p_w1_h, *p_w1_l, *p_w2_h, *p_w2_l;
    cudaGetSymbolAddress((void**)&p_xw_h,  g_xw_h);
    cudaGetSymbolAddress((void**)&p_xw_l,  g_xw_l);
    cudaGetSymbolAddress((void**)&p_qkv,   g_qkv);
    cudaGetSymbolAddress((void**)&p_att_h, g_att_h);
    cudaGetSymbolAddress((void**)&p_att_l, g_att_l);
    cudaGetSymbolAddress((void**)&p_proj,  g_proj);
    cudaGetSymbolAddress((void**)&p_x2,    g_x2);
    cudaGetSymbolAddress((void**)&p_h2_h,  g_h2_h);
    cudaGetSymbolAddress((void**)&p_h2_l,  g_h2_l);
    cudaGetSymbolAddress((void**)&p_ffn_h, g_ffn_h);
    cudaGetSymbolAddress((void**)&p_ffn_l, g_ffn_l);
    cudaGetSymbolAddress((void**)&p_wqkv_h,  g_wqkv_h);
    cudaGetSymbolAddress((void**)&p_wqkv_l,  g_wqkv_l);
    cudaGetSymbolAddress((void**)&p_wproj_h, g_wproj_h);
    cudaGetSymbolAddress((void**)&p_wproj_l, g_wproj_l);
    cudaGetSymbolAddress((void**)&p_w1_h,    g_w1_h);
    cudaGetSymbolAddress((void**)&p_w1_l,    g_w1_l);
    cudaGetSymbolAddress((void**)&p_w2_h,    g_w2_h);
    cudaGetSymbolAddress((void**)&p_w2_l,    g_w2_l);

    cudaFuncSetAttribute(hmma_gemm<0>, cudaFuncAttributeMaxDynamicSharedMemorySize, GSMEM);
    cudaFuncSetAttribute(hmma_gemm<1>, cudaFuncAttributeMaxDynamicSharedMemorySize, GSMEM);
    cudaFuncSetAttribute(hmma_gemm<2>, cudaFuncAttributeMaxDynamicSharedMemorySize, GSMEM);

    // weight prep (tiled transpose + bf16 hi/lo split)
    prep_w<<<dim3((3*CH)/32, CH/32), 256>>>(w_qkv, p_wqkv_h, p_wqkv_l, CH, 3*CH);
    prep_w<<<dim3(CH/32,     CH/32), 256>>>(w_proj, p_wproj_h, p_wproj_l, CH, CH);
    prep_w<<<dim3(CFF/32,    CH/32), 256>>>(w1, p_w1_h, p_w1_l, CH, CFF);
    prep_w<<<dim3(CH/32,    CFF/32), 256>>>(w2, p_w2_h, p_w2_l, CFF, CH);

    // 1. LN1 + shift + window partition -> bf16 hi/lo
    ln1_window_kernel<<<NTOK, 256>>>(x, g1, be1, p_xw_h, p_xw_l);

    // 2. QKV GEMM
    hmma_gemm<0><<<dim3((3*CH)/128, NTOK/128), 256, GSMEM>>>(
        p_xw_h, p_xw_l, p_wqkv_h, p_wqkv_l, b_qkv, nullptr,
        p_qkv, nullptr, nullptr, CH, 3*CH);

    // 3. windowed attention -> bf16 hi/lo
    attn_kernel<<<NWIN * NHEAD, 128>>>(p_qkv, bias_table, p_att_h, p_att_l);

    // 4. proj GEMM
    hmma_gemm<0><<<dim3(CH/128, NTOK/128), 256, GSMEM>>>(
        p_att_h, p_att_l, p_wproj_h, p_wproj_l, b_proj, nullptr,
        p_proj, nullptr, nullptr, CH, CH);

    // 5. window reverse + roll + residual + LN2 -> x2 fp32 + h2 bf16 hi/lo
    res_ln2_kernel<<<NTOK, 256>>>(x, p_proj, g2, be2, p_x2, p_h2_h, p_h2_l);

    // 6. FFN1 + GELU -> bf16 hi/lo
    hmma_gemm<1><<<dim3(CFF/128, NTOK/128), 256, GSMEM>>>(
        p_h2_h, p_h2_l, p_w1_h, p_w1_l, b1, nullptr,
        nullptr, p_ffn_h, p_ffn_l, CH, CFF);

    // 7. FFN2 + residual -> out
    hmma_gemm<2><<<dim3(CH/128, NTOK/128), 256, GSMEM>>>(
        p_ffn_h, p_ffn_l, p_w2_h, p_w2_l, b2, p_x2,
        out, nullptr, nullptr, CFF, CH);
}

// round 6
// speedup vs baseline: 2.9938x; 1.6042x over previous
#include <cuda_runtime.h>
#include <cuda_fp16.h>
#include <math.h>
#include <stdint.h>

// ---------------- problem constants ----------------
#define BATCH 16
#define HDIM  56
#define WDIM  56
#define CH    512
#define CFF   2048
#define NHEAD 16
#define DH    32
#define MWIN  7
#define NTOKW 49
#define SHIFT 3
#define NTOK  (BATCH*HDIM*WDIM)                  // 50176
#define NWIN  (BATCH*(HDIM/MWIN)*(WDIM/MWIN))    // 1024

// ---------------- device scratch (allocation-free) ----------------
__device__ half  g_xw  [(size_t)NTOK*CH];
__device__ half  g_qkv [(size_t)NTOK*3*CH];
__device__ half  g_att [(size_t)NTOK*CH];
__device__ float g_proj[(size_t)NTOK*CH];
__device__ float g_x2  [(size_t)NTOK*CH];
__device__ half  g_h2  [(size_t)NTOK*CH];
__device__ half  g_ffn [(size_t)NTOK*CFF];
// weights transposed to [N,K] fp16
__device__ half g_wqkv [(size_t)CH*3*CH];
__device__ half g_wproj[(size_t)CH*CH];
__device__ half g_w1   [(size_t)CH*CFF];
__device__ half g_w2   [(size_t)CFF*CH];

// ---------------- PTX helpers ----------------
__device__ __forceinline__ uint32_t smem_u32(const void* p){
    uint32_t a;
    asm("{ .reg .u64 t; cvta.to.shared.u64 t, %1; cvt.u32.u64 %0, t; }" : "=r"(a) : "l"(p));
    return a;
}
#define CP_ASYNC16(dst, src) \
    asm volatile("cp.async.cg.shared.global [%0], [%1], 16;" :: "r"(dst), "l"(src))
#define CP_COMMIT() asm volatile("cp.async.commit_group;" ::: "memory")
#define CP_WAIT(N)  asm volatile("cp.async.wait_group %0;" :: "n"(N) : "memory")

#define LDSM_X4(r, a) \
    asm volatile("ldmatrix.sync.aligned.m8n8.x4.shared.b16 {%0,%1,%2,%3}, [%4];" \
        : "=r"((r)[0]), "=r"((r)[1]), "=r"((r)[2]), "=r"((r)[3]) : "r"(a))

#define MMA_F16(d, a, b0, b1) \
    asm volatile("mma.sync.aligned.m16n8k16.row.col.f32.f16.f16.f32 " \
        "{%0,%1,%2,%3}, {%4,%5,%6,%7}, {%8,%9}, {%0,%1,%2,%3};" \
        : "+f"((d)[0]), "+f"((d)[1]), "+f"((d)[2]), "+f"((d)[3]) \
        : "r"((a)[0]), "r"((a)[1]), "r"((a)[2]), "r"((a)[3]), "r"(b0), "r"(b1))

// ---------------- fp16 HMMA GEMM ----------------
// C[M,N] = A @ B^T + bias ; A: [M,K] fp16, B: [N,K] fp16, fp32 accumulate.
// CTA tile 128x128, BK=32, rows padded to 80B (conflict-free ldmatrix:
// bank-quad = (5r+c) mod 8 is a permutation over 8 rows).
// EPI=0: fp32 out. EPI=1: GELU -> fp16 out. EPI=2: +res -> fp32 out. EPI=3: fp16 out.
#define TILEB  10240
#define STAGEB 20480
#define GSMEM  (2*STAGEB)

template<int EPI>
__global__ __launch_bounds__(256, 2) void hmma_gemm(
    const half* __restrict__ Ag, const half* __restrict__ Bg,
    const float* __restrict__ bias, const float* __restrict__ res,
    float* __restrict__ Cf, half* __restrict__ Ch,
    int K, int Nc)
{
    extern __shared__ char smem[];
    const int tid = threadIdx.x;
    const int lane = tid & 31, wid = tid >> 5;
    const int wm = wid & 1, wn = wid >> 1;          // warp tile: 64 x 32

    const half* Ab = Ag + (size_t)blockIdx.y * 128 * K;
    const half* Bb = Bg + (size_t)blockIdx.x * 128 * K;

    const uint32_t sb = smem_u32(smem);
    const int NK = K >> 5;

    float acc[4][4][4];
    #pragma unroll
    for (int a = 0; a < 4; a++)
        #pragma unroll
        for (int b = 0; b < 4; b++)
            #pragma unroll
            for (int c = 0; c < 4; c++) acc[a][b][c] = 0.f;

    const int lr0 = tid >> 2;          // 0..63
    const int lc  = tid & 3;           // 16B chunk 0..3
    auto load_stage = [&](int kb, int s) {
        uint32_t st = sb + (uint32_t)s * STAGEB;
        #pragma unroll
        for (int i = 0; i < 4; i++) {
            const int t = i >> 1;
            int r = (i & 1) * 64 + lr0;
            const half* src = (t ? Bb : Ab) + (size_t)r * K + kb * 32 + lc * 8;
            uint32_t dst = st + (uint32_t)(t * TILEB + r * 80 + lc * 16);
            CP_ASYNC16(dst, src);
        }
        CP_COMMIT();
    };

    auto compute_stage = [&](int s) {
        uint32_t st = sb + (uint32_t)s * STAGEB;
        #pragma unroll
        for (int kk = 0; kk < 2; kk++) {
            const int ch = kk * 2 + (lane >> 4);
            uint32_t bh[2][4];
            #pragma unroll
            for (int np = 0; np < 2; np++) {
                int row = wn * 32 + np * 16 + (lane & 15);
                uint32_t off = (uint32_t)(row * 80 + ch * 16);
                LDSM_X4(bh[np], st + 1u * TILEB + off);
            }
            #pragma unroll
            for (int mt = 0; mt < 4; mt++) {
                int row = wm * 64 + mt * 16 + (lane & 15);
                uint32_t off = (uint32_t)(row * 80 + ch * 16);
                uint32_t ah[4];
                LDSM_X4(ah, st + off);
                #pragma unroll
                for (int nt = 0; nt < 4; nt++) {
                    int np = nt >> 1, se = nt & 1;
                    MMA_F16(acc[mt][nt], ah, bh[np][se], bh[np][se + 2]);
                }
            }
        }
    };

    load_stage(0, 0);
    for (int kb = 0; kb < NK; kb++) {
        int cur = kb & 1;
        if (kb + 1 < NK) {
            load_stage(kb + 1, cur ^ 1);
            CP_WAIT(1);
        } else {
            CP_WAIT(0);
        }
        __syncthreads();
        compute_stage(cur);
        __syncthreads();
    }

    // --- epilogue: registers -> gmem ---
    int row0 = blockIdx.y * 128 + wm * 64;
    int col0 = blockIdx.x * 128 + wn * 32;
    #pragma unroll
    for (int mt = 0; mt < 4; mt++) {
        #pragma unroll
        for (int nt = 0; nt < 4; nt++) {
            int c = col0 + nt * 8 + (lane & 3) * 2;
            float b0 = bias[c], b1 = bias[c + 1];
            #pragma unroll
            for (int h = 0; h < 2; h++) {
                int r = row0 + mt * 16 + (lane >> 2) + h * 8;
                float v0 = acc[mt][nt][h * 2]     + b0;
                float v1 = acc[mt][nt][h * 2 + 1] + b1;
                size_t o = (size_t)r * Nc + c;
                if (EPI == 1) {
                    v0 = 0.5f * v0 * (1.0f + erff(v0 * 0.70710678118654752f));
                    v1 = 0.5f * v1 * (1.0f + erff(v1 * 0.70710678118654752f));
                    *(half2*)(Ch + o) = __floats2half2_rn(v0, v1);
                } else if (EPI == 3) {
                    *(half2*)(Ch + o) = __floats2half2_rn(v0, v1);
                } else {
                    if (EPI == 2) {
                        float2 rv = *(const float2*)(res + o);
                        v0 += rv.x; v1 += rv.y;
                    }
                    *(float2*)(Cf + o) = make_float2(v0, v1);
                }
            }
        }
    }
}

// ---------------- weight prep: [K,N] fp32 -> [N,K] fp16 (tiled transpose) ----------------
__global__ __launch_bounds__(256) void prep_w(
    const float* __restrict__ W, half* __restrict__ Wh, int K, int N)
{
    __shared__ float tile[32][33];
    int nb = blockIdx.x * 32, kb = blockIdx.y * 32;
    int tx = threadIdx.x & 31, ty = threadIdx.x >> 5;  // 32 x 8
    #pragma unroll
    for (int j = 0; j < 32; j += 8)
        tile[ty + j][tx] = W[(size_t)(kb + ty + j) * N + nb + tx];
    __syncthreads();
    #pragma unroll
    for (int j = 0; j < 32; j += 8)
        Wh[(size_t)(nb + ty + j) * K + kb + tx] = __float2half_rn(tile[tx][ty + j]);
}

// ---------------- block reduction (256 threads) ----------------
__device__ __forceinline__ void block_reduce_2(float& s, float& sq) {
    __shared__ float sh[16];
    int lane = threadIdx.x & 31, wid = threadIdx.x >> 5;
    #pragma unroll
    for (int o = 16; o > 0; o >>= 1) {
        s  += __shfl_down_sync(0xffffffffu, s,  o);
        sq += __shfl_down_sync(0xffffffffu, sq, o);
    }
    if (lane == 0) { sh[wid] = s; sh[wid + 8] = sq; }
    __syncthreads();
    if (threadIdx.x == 0) {
        float S = 0.f, SQ = 0.f;
        #pragma unroll
        for (int i = 0; i < 8; i++) { S += sh[i]; SQ += sh[i + 8]; }
        sh[0] = S; sh[8] = SQ;
    }
    __syncthreads();
    s = sh[0]; sq = sh[8];
}

// ---------------- LN1 + shift + window partition -> fp16 ----------------
__global__ __launch_bounds__(256) void ln1_window_kernel(
    const float* __restrict__ x, const float* __restrict__ g, const float* __restrict__ b,
    half* __restrict__ out)
{
    int t = blockIdx.x;
    int w = t / NTOKW, tok = t - w * NTOKW;
    int bb = w >> 6, wrem = w & 63;
    int wi = wrem >> 3, wj = wrem & 7;
    int ti = tok / MWIN, tj = tok - ti * MWIN;
    int r = (wi * MWIN + ti + SHIFT) % HDIM;
    int c = (wj * MWIN + tj + SHIFT) % WDIM;
    const float* src = x + ((size_t)bb * (HDIM * WDIM) + r * WDIM + c) * CH;
    int tid = threadIdx.x;
    float v0 = src[tid], v1 = src[tid + 256];
    float s = v0 + v1, sq = v0 * v0 + v1 * v1;
    block_reduce_2(s, sq);
    float mu  = s * (1.0f / CH);
    float var = sq * (1.0f / CH) - mu * mu;
    float inv = rsqrtf(var + 1e-5f);
    size_t base = (size_t)t * CH;
    out[base + tid]       = __float2half_rn((v0 - mu) * inv * g[tid]       + b[tid]);
    out[base + tid + 256] = __float2half_rn((v1 - mu) * inv * g[tid + 256] + b[tid + 256]);
}

// ---------------- windowed attention (fp16 in/out, fp32 math) ----------------
__global__ __launch_bounds__(128) void attn_kernel(
    const half* __restrict__ qkv, const float* __restrict__ bias_table,
    half* __restrict__ out)
{
    int win  = blockIdx.x >> 4;
    int head = blockIdx.x & 15;
    __shared__ float q[NTOKW][DH], kk[NTOKW][DH], v[NTOKW][DH];
    __shared__ float sc[NTOKW][NTOKW + 1];
    int tid = threadIdx.x;
    const float scale = 0.17677669529663687f;
    size_t base = (size_t)win * NTOKW * (3 * CH) + head * DH;
    for (int i = tid; i < NTOKW * DH; i += 128) {
        int n = i / DH, d = i - n * DH;
        size_t rb = base + (size_t)n * (3 * CH);
        q[n][d]  = __half2float(qkv[rb + d]);
        kk[n][d] = __half2float(qkv[rb + CH + d]);
        v[n][d]  = __half2float(qkv[rb + 2 * CH + d]);
    }
    __syncthreads();
    for (int i = tid; i < NTOKW * NTOKW; i += 128) {
        int n = i / NTOKW, m = i - n * NTOKW;
        float s = 0.f;
        #pragma unroll
        for (int d = 0; d < DH; d++) s = fmaf(q[n][d], kk[m][d], s);
        int dr = n / MWIN - m / MWIN + (MWIN - 1);
        int dc = n % MWIN - m % MWIN + (MWIN - 1);
        sc[n][m] = s * scale + bias_table[(dr * (2 * MWIN - 1) + dc) * NHEAD + head];
    }
    __syncthreads();
    if (tid < NTOKW) {
        float mx = -1e30f;
        #pragma unroll 7
        for (int m = 0; m < NTOKW; m++) mx = fmaxf(mx, sc[tid][m]);
        float sum = 0.f;
        #pragma unroll 7
        for (int m = 0; m < NTOKW; m++) { float e = expf(sc[tid][m] - mx); sc[tid][m] = e; sum += e; }
        float inv = 1.0f / sum;
        #pragma unroll 7
        for (int m = 0; m < NTOKW; m++) sc[tid][m] *= inv;
    }
    __syncthreads();
    for (int i = tid; i < NTOKW * DH; i += 128) {
        int n = i / DH, d = i - n * DH;
        float s = 0.f;
        #pragma unroll 7
        for (int m = 0; m < NTOKW; m++) s = fmaf(sc[n][m], v[m][d], s);
        out[((size_t)win * NTOKW + n) * CH + head * DH + d] = __float2half_rn(s);
    }
}

// ---------------- window reverse + roll + residual + LN2 ----------------
__global__ __launch_bounds__(256) void res_ln2_kernel(
    const float* __restrict__ x, const float* __restrict__ proj,
    const float* __restrict__ g, const float* __restrict__ b,
    float* __restrict__ x2, half* __restrict__ h2)
{
    int t = blockIdx.x;
    int bb = t / (HDIM * WDIM);
    int rc = t - bb * (HDIM * WDIM);
    int r = rc / WDIM, c = rc - r * WDIM;
    int rs = (r - SHIFT + HDIM) % HDIM;
    int cs = (c - SHIFT + WDIM) % WDIM;
    int w   = bb * 64 + (rs / MWIN) * 8 + (cs / MWIN);
    int tok = (rs % MWIN) * MWIN + (cs % MWIN);
    const float* ps = proj + ((size_t)w * NTOKW + tok) * CH;
    const float* xs = x + (size_t)t * CH;
    int tid = threadIdx.x;
    float v0 = xs[tid] + ps[tid];
    float v1 = xs[tid + 256] + ps[tid + 256];
    float* x2p = x2 + (size_t)t * CH;
    x2p[tid] = v0; x2p[tid + 256] = v1;
    float s = v0 + v1, sq = v0 * v0 + v1 * v1;
    block_reduce_2(s, sq);
    float mu  = s * (1.0f / CH);
    float var = sq * (1.0f / CH) - mu * mu;
    float inv = rsqrtf(var + 1e-5f);
    size_t base = (size_t)t * CH;
    h2[base + tid]       = __float2half_rn((v0 - mu) * inv * g[tid]       + b[tid]);
    h2[base + tid + 256] = __float2half_rn((v1 - mu) * inv * g[tid + 256] + b[tid + 256]);
}

// ---------------- launcher ----------------
extern "C" void kernel_launch(void* const* d_in, const int* in_sizes, int n_in,
                              void* d_out, int out_size)
{
    const float* x          = (const float*)d_in[0];
    const float* w_qkv      = (const float*)d_in[3];
    const float* b_qkv      = (const float*)d_in[4];
    const float* w_proj     = (const float*)d_in[5];
    const float* b_proj     = (const float*)d_in[6];
    const float* bias_table = (const float*)d_in[7];
    const float* g1         = (const float*)d_in[8];
    const float* be1        = (const float*)d_in[9];
    const float* g2         = (const float*)d_in[10];
    const float* be2        = (const float*)d_in[11];
    const float* w1         = (const float*)d_in[12];
    const float* b1         = (const float*)d_in[13];
    const float* w2         = (const float*)d_in[14];
    const float* b2         = (const float*)d_in[15];
    float* out = (float*)d_out;

    half *p_xw, *p_qkv, *p_att, *p_h2, *p_ffn;
    float *p_proj, *p_x2;
    half *p_wqkv, *p_wproj, *p_w1, *p_w2;
    cudaGetSymbolAddress((void**)&p_xw,   g_xw);
    cudaGetSymbolAddress((void**)&p_qkv,  g_qkv);
    cudaGetSymbolAddress((void**)&p_att,  g_att);
    cudaGetSymbolAddress((void**)&p_proj, g_proj);
    cudaGetSymbolAddress((void**)&p_x2,   g_x2);
    cudaGetSymbolAddress((void**)&p_h2,   g_h2);
    cudaGetSymbolAddress((void**)&p_ffn,  g_ffn);
    cudaGetSymbolAddress((void**)&p_wqkv,  g_wqkv);
    cudaGetSymbolAddress((void**)&p_wproj, g_wproj);
    cudaGetSymbolAddress((void**)&p_w1,    g_w1);
    cudaGetSymbolAddress((void**)&p_w2,    g_w2);

    cudaFuncSetAttribute(hmma_gemm<0>, cudaFuncAttributeMaxDynamicSharedMemorySize, GSMEM);
    cudaFuncSetAttribute(hmma_gemm<1>, cudaFuncAttributeMaxDynamicSharedMemorySize, GSMEM);
    cudaFuncSetAttribute(hmma_gemm<2>, cudaFuncAttributeMaxDynamicSharedMemorySize, GSMEM);
    cudaFuncSetAttribute(hmma_gemm<3>, cudaFuncAttributeMaxDynamicSharedMemorySize, GSMEM);

    // weight prep (tiled transpose to fp16)
    prep_w<<<dim3((3*CH)/32, CH/32), 256>>>(w_qkv, p_wqkv, CH, 3*CH);
    prep_w<<<dim3(CH/32,     CH/32), 256>>>(w_proj, p_wproj, CH, CH);
    prep_w<<<dim3(CFF/32,    CH/32), 256>>>(w1, p_w1, CH, CFF);
    prep_w<<<dim3(CH/32,    CFF/32), 256>>>(w2, p_w2, CFF, CH);

    // 1. LN1 + shift + window partition -> fp16
    ln1_window_kernel<<<NTOK, 256>>>(x, g1, be1, p_xw);

    // 2. QKV GEMM -> fp16 (bias only)
    hmma_gemm<3><<<dim3((3*CH)/128, NTOK/128), 256, GSMEM>>>(
        p_xw, p_wqkv, b_qkv, nullptr, nullptr, p_qkv, CH, 3*CH);

    // 3. windowed attention -> fp16
    attn_kernel<<<NWIN * NHEAD, 128>>>(p_qkv, bias_table, p_att);

    // 4. proj GEMM -> fp32
    hmma_gemm<0><<<dim3(CH/128, NTOK/128), 256, GSMEM>>>(
        p_att, p_wproj, b_proj, nullptr, p_proj, nullptr, CH, CH);

    // 5. window reverse + roll + residual + LN2
    res_ln2_kernel<<<NTOK, 256>>>(x, p_proj, g2, be2, p_x2, p_h2);

    // 6. FFN1 + GELU -> fp16
    hmma_gemm<1><<<dim3(CFF/128, NTOK/128), 256, GSMEM>>>(
        p_h2, p_w1, b1, nullptr, nullptr, p_ffn, CH, CFF);

    // 7. FFN2 + residual -> out
    hmma_gemm<2><<<dim3(CH/128, NTOK/128), 256, GSMEM>>>(
        p_ffn, p_w2, b2, p_x2, out, nullptr, CFF, CH);
}

// round 7
// speedup vs baseline: 4.1488x; 1.3858x over previous
#include <cuda_runtime.h>
#include <cuda_fp16.h>
#include <math.h>
#include <stdint.h>

// ---------------- problem constants ----------------
#define BATCH 16
#define HDIM  56
#define WDIM  56
#define CH    512
#define CFF   2048
#define NHEAD 16
#define DH    32
#define MWIN  7
#define NTOKW 49
#define SHIFT 3
#define NTOK  (BATCH*HDIM*WDIM)                  // 50176
#define NWIN  (BATCH*(HDIM/MWIN)*(WDIM/MWIN))    // 1024

// ---------------- device scratch (allocation-free) ----------------
__device__ half  g_xw  [(size_t)NTOK*CH];
__device__ half  g_qkv [(size_t)NTOK*3*CH];
__device__ half  g_att [(size_t)NTOK*CH];
__device__ float g_proj[(size_t)NTOK*CH];
__device__ float g_x2  [(size_t)NTOK*CH];
__device__ half  g_h2  [(size_t)NTOK*CH];
__device__ half  g_ffn [(size_t)NTOK*CFF];
// weights transposed to [N,K] fp16
__device__ half g_wqkv [(size_t)CH*3*CH];
__device__ half g_wproj[(size_t)CH*CH];
__device__ half g_w1   [(size_t)CH*CFF];
__device__ half g_w2   [(size_t)CFF*CH];

// ---------------- PTX helpers ----------------
__device__ __forceinline__ uint32_t smem_u32(const void* p){
    uint32_t a;
    asm("{ .reg .u64 t; cvta.to.shared.u64 t, %1; cvt.u32.u64 %0, t; }" : "=r"(a) : "l"(p));
    return a;
}
#define CP_ASYNC16(dst, src) \
    asm volatile("cp.async.cg.shared.global [%0], [%1], 16;" :: "r"(dst), "l"(src))
#define CP_COMMIT() asm volatile("cp.async.commit_group;" ::: "memory")
#define CP_WAIT(N)  asm volatile("cp.async.wait_group %0;" :: "n"(N) : "memory")

#define LDSM_X4(r, a) \
    asm volatile("ldmatrix.sync.aligned.m8n8.x4.shared.b16 {%0,%1,%2,%3}, [%4];" \
        : "=r"((r)[0]), "=r"((r)[1]), "=r"((r)[2]), "=r"((r)[3]) : "r"(a))

#define MMA_F16(d, a, b0, b1) \
    asm volatile("mma.sync.aligned.m16n8k16.row.col.f32.f16.f16.f32 " \
        "{%0,%1,%2,%3}, {%4,%5,%6,%7}, {%8,%9}, {%0,%1,%2,%3};" \
        : "+f"((d)[0]), "+f"((d)[1]), "+f"((d)[2]), "+f"((d)[3]) \
        : "r"((a)[0]), "r"((a)[1]), "r"((a)[2]), "r"((a)[3]), "r"(b0), "r"(b1))

// ---------------- fp16 HMMA GEMM, 4-stage cp.async pipeline ----------------
// C[M,N] = A @ B^T + bias ; A: [M,K] fp16, B: [N,K] fp16, fp32 accumulate.
// CTA tile 128x128, BK=32, rows padded to 80B (conflict-free ldmatrix:
// bank-quad = (5r+c) mod 8 is a permutation over 8 rows).
// Stage = 2 tiles x 128 rows x 80B = 20KB; 4 stages = 80KB -> 2 CTAs/SM.
// EPI=0: fp32 out. EPI=1: GELU -> fp16 out. EPI=2: +res -> fp32 out. EPI=3: fp16 out.
#define TILEB  10240
#define STAGEB 20480
#define GSMEM  (4*STAGEB)

template<int EPI>
__global__ __launch_bounds__(256, 2) void hmma_gemm(
    const half* __restrict__ Ag, const half* __restrict__ Bg,
    const float* __restrict__ bias, const float* __restrict__ res,
    float* __restrict__ Cf, half* __restrict__ Ch,
    int K, int Nc)
{
    extern __shared__ char smem[];
    const int tid = threadIdx.x;
    const int lane = tid & 31, wid = tid >> 5;
    const int wm = wid & 1, wn = wid >> 1;          // warp tile: 64 x 32

    const half* Ab = Ag + (size_t)blockIdx.y * 128 * K;
    const half* Bb = Bg + (size_t)blockIdx.x * 128 * K;

    const uint32_t sb = smem_u32(smem);
    const int NK = K >> 5;

    float acc[4][4][4];
    #pragma unroll
    for (int a = 0; a < 4; a++)
        #pragma unroll
        for (int b = 0; b < 4; b++)
            #pragma unroll
            for (int c = 0; c < 4; c++) acc[a][b][c] = 0.f;

    const int lr0 = tid >> 2;          // 0..63
    const int lc  = tid & 3;           // 16B chunk 0..3
    auto load_stage = [&](int kb, int s) {
        uint32_t st = sb + (uint32_t)s * STAGEB;
        #pragma unroll
        for (int i = 0; i < 4; i++) {
            const int t = i >> 1;
            int r = (i & 1) * 64 + lr0;
            const half* src = (t ? Bb : Ab) + (size_t)r * K + kb * 32 + lc * 8;
            uint32_t dst = st + (uint32_t)(t * TILEB + r * 80 + lc * 16);
            CP_ASYNC16(dst, src);
        }
        CP_COMMIT();
    };

    auto compute_stage = [&](int s) {
        uint32_t st = sb + (uint32_t)s * STAGEB;
        #pragma unroll
        for (int kk = 0; kk < 2; kk++) {
            const int ch = kk * 2 + (lane >> 4);
            uint32_t bh[2][4];
            #pragma unroll
            for (int np = 0; np < 2; np++) {
                int row = wn * 32 + np * 16 + (lane & 15);
                uint32_t off = (uint32_t)(row * 80 + ch * 16);
                LDSM_X4(bh[np], st + 1u * TILEB + off);
            }
            #pragma unroll
            for (int mt = 0; mt < 4; mt++) {
                int row = wm * 64 + mt * 16 + (lane & 15);
                uint32_t off = (uint32_t)(row * 80 + ch * 16);
                uint32_t ah[4];
                LDSM_X4(ah, st + off);
                #pragma unroll
                for (int nt = 0; nt < 4; nt++) {
                    int np = nt >> 1, se = nt & 1;
                    MMA_F16(acc[mt][nt], ah, bh[np][se], bh[np][se + 2]);
                }
            }
        }
    };

    // prologue: fill 3 stages
    load_stage(0, 0);
    if (NK > 1) load_stage(1, 1);
    if (NK > 2) load_stage(2, 2);

    for (int kb = 0; kb < NK; kb++) {
        // ensure stage kb has arrived (retain the right number of in-flight groups)
        if (kb + 3 <= NK) { CP_WAIT(2); }
        else if (kb + 2 == NK) { CP_WAIT(1); }
        else { CP_WAIT(0); }
        __syncthreads();   // also guards reuse of slot (kb+3)&3 against compute(kb-1)
        if (kb + 3 < NK) load_stage(kb + 3, (kb + 3) & 3);
        compute_stage(kb & 3);
    }

    // --- epilogue: registers -> gmem ---
    int row0 = blockIdx.y * 128 + wm * 64;
    int col0 = blockIdx.x * 128 + wn * 32;
    #pragma unroll
    for (int mt = 0; mt < 4; mt++) {
        #pragma unroll
        for (int nt = 0; nt < 4; nt++) {
            int c = col0 + nt * 8 + (lane & 3) * 2;
            float b0 = bias[c], b1 = bias[c + 1];
            #pragma unroll
            for (int h = 0; h < 2; h++) {
                int r = row0 + mt * 16 + (lane >> 2) + h * 8;
                float v0 = acc[mt][nt][h * 2]     + b0;
                float v1 = acc[mt][nt][h * 2 + 1] + b1;
                size_t o = (size_t)r * Nc + c;
                if (EPI == 1) {
                    v0 = 0.5f * v0 * (1.0f + erff(v0 * 0.70710678118654752f));
                    v1 = 0.5f * v1 * (1.0f + erff(v1 * 0.70710678118654752f));
                    *(half2*)(Ch + o) = __floats2half2_rn(v0, v1);
                } else if (EPI == 3) {
                    *(half2*)(Ch + o) = __floats2half2_rn(v0, v1);
                } else {
                    if (EPI == 2) {
                        float2 rv = *(const float2*)(res + o);
                        v0 += rv.x; v1 += rv.y;
                    }
                    *(float2*)(Cf + o) = make_float2(v0, v1);
                }
            }
        }
    }
}

// ---------------- weight prep: [K,N] fp32 -> [N,K] fp16 (tiled transpose) ----------------
__global__ __launch_bounds__(256) void prep_w(
    const float* __restrict__ W, half* __restrict__ Wh, int K, int N)
{
    __shared__ float tile[32][33];
    int nb = blockIdx.x * 32, kb = blockIdx.y * 32;
    int tx = threadIdx.x & 31, ty = threadIdx.x >> 5;  // 32 x 8
    #pragma unroll
    for (int j = 0; j < 32; j += 8)
        tile[ty + j][tx] = W[(size_t)(kb + ty + j) * N + nb + tx];
    __syncthreads();
    #pragma unroll
    for (int j = 0; j < 32; j += 8)
        Wh[(size_t)(nb + ty + j) * K + kb + tx] = __float2half_rn(tile[tx][ty + j]);
}

// ---------------- block reduction (256 threads) ----------------
__device__ __forceinline__ void block_reduce_2(float& s, float& sq) {
    __shared__ float sh[16];
    int lane = threadIdx.x & 31, wid = threadIdx.x >> 5;
    #pragma unroll
    for (int o = 16; o > 0; o >>= 1) {
        s  += __shfl_down_sync(0xffffffffu, s,  o);
        sq += __shfl_down_sync(0xffffffffu, sq, o);
    }
    if (lane == 0) { sh[wid] = s; sh[wid + 8] = sq; }
    __syncthreads();
    if (threadIdx.x == 0) {
        float S = 0.f, SQ = 0.f;
        #pragma unroll
        for (int i = 0; i < 8; i++) { S += sh[i]; SQ += sh[i + 8]; }
        sh[0] = S; sh[8] = SQ;
    }
    __syncthreads();
    s = sh[0]; sq = sh[8];
}

// ---------------- LN1 + shift + window partition -> fp16 ----------------
__global__ __launch_bounds__(256) void ln1_window_kernel(
    const float* __restrict__ x, const float* __restrict__ g, const float* __restrict__ b,
    half* __restrict__ out)
{
    int t = blockIdx.x;
    int w = t / NTOKW, tok = t - w * NTOKW;
    int bb = w >> 6, wrem = w & 63;
    int wi = wrem >> 3, wj = wrem & 7;
    int ti = tok / MWIN, tj = tok - ti * MWIN;
    int r = (wi * MWIN + ti + SHIFT) % HDIM;
    int c = (wj * MWIN + tj + SHIFT) % WDIM;
    const float* src = x + ((size_t)bb * (HDIM * WDIM) + r * WDIM + c) * CH;
    int tid = threadIdx.x;
    float v0 = src[tid], v1 = src[tid + 256];
    float s = v0 + v1, sq = v0 * v0 + v1 * v1;
    block_reduce_2(s, sq);
    float mu  = s * (1.0f / CH);
    float var = sq * (1.0f / CH) - mu * mu;
    float inv = rsqrtf(var + 1e-5f);
    size_t base = (size_t)t * CH;
    out[base + tid]       = __float2half_rn((v0 - mu) * inv * g[tid]       + b[tid]);
    out[base + tid + 256] = __float2half_rn((v1 - mu) * inv * g[tid + 256] + b[tid + 256]);
}

// ---------------- windowed attention (fp16 in/out, fp32 math) ----------------
// kk/v padded to 33 floats per row: bank = (m*33+d) % 32 = (m+d) % 32 varies
// with m -> conflict-free gathers in the QK^T loop.
__global__ __launch_bounds__(128) void attn_kernel(
    const half* __restrict__ qkv, const float* __restrict__ bias_table,
    half* __restrict__ out)
{
    int win  = blockIdx.x >> 4;
    int head = blockIdx.x & 15;
    __shared__ float q[NTOKW][DH];
    __shared__ float kk[NTOKW][DH + 1], v[NTOKW][DH + 1];
    __shared__ float sc[NTOKW][NTOKW + 1];
    int tid = threadIdx.x;
    const float scale = 0.17677669529663687f;
    size_t base = (size_t)win * NTOKW * (3 * CH) + head * DH;
    for (int i = tid; i < NTOKW * DH; i += 128) {
        int n = i / DH, d = i - n * DH;
        size_t rb = base + (size_t)n * (3 * CH);
        q[n][d]  = __half2float(qkv[rb + d]);
        kk[n][d] = __half2float(qkv[rb + CH + d]);
        v[n][d]  = __half2float(qkv[rb + 2 * CH + d]);
    }
    __syncthreads();
    for (int i = tid; i < NTOKW * NTOKW; i += 128) {
        int n = i / NTOKW, m = i - n * NTOKW;
        float s = 0.f;
        #pragma unroll
        for (int d = 0; d < DH; d++) s = fmaf(q[n][d], kk[m][d], s);
        int dr = n / MWIN - m / MWIN + (MWIN - 1);
        int dc = n % MWIN - m % MWIN + (MWIN - 1);
        sc[n][m] = s * scale + bias_table[(dr * (2 * MWIN - 1) + dc) * NHEAD + head];
    }
    __syncthreads();
    if (tid < NTOKW) {
        float mx = -1e30f;
        #pragma unroll 7
        for (int m = 0; m < NTOKW; m++) mx = fmaxf(mx, sc[tid][m]);
        float sum = 0.f;
        #pragma unroll 7
        for (int m = 0; m < NTOKW; m++) { float e = expf(sc[tid][m] - mx); sc[tid][m] = e; sum += e; }
        float inv = 1.0f / sum;
        #pragma unroll 7
        for (int m = 0; m < NTOKW; m++) sc[tid][m] *= inv;
    }
    __syncthreads();
    for (int i = tid; i < NTOKW * DH; i += 128) {
        int n = i / DH, d = i - n * DH;
        float s = 0.f;
        #pragma unroll 7
        for (int m = 0; m < NTOKW; m++) s = fmaf(sc[n][m], v[m][d], s);
        out[((size_t)win * NTOKW + n) * CH + head * DH + d] = __float2half_rn(s);
    }
}

// ---------------- window reverse + roll + residual + LN2 ----------------
__global__ __launch_bounds__(256) void res_ln2_kernel(
    const float* __restrict__ x, const float* __restrict__ proj,
    const float* __restrict__ g, const float* __restrict__ b,
    float* __restrict__ x2, half* __restrict__ h2)
{
    int t = blockIdx.x;
    int bb = t / (HDIM * WDIM);
    int rc = t - bb * (HDIM * WDIM);
    int r = rc / WDIM, c = rc - r * WDIM;
    int rs = (r - SHIFT + HDIM) % HDIM;
    int cs = (c - SHIFT + WDIM) % WDIM;
    int w   = bb * 64 + (rs / MWIN) * 8 + (cs / MWIN);
    int tok = (rs % MWIN) * MWIN + (cs % MWIN);
    const float* ps = proj + ((size_t)w * NTOKW + tok) * CH;
    const float* xs = x + (size_t)t * CH;
    int tid = threadIdx.x;
    float v0 = xs[tid] + ps[tid];
    float v1 = xs[tid + 256] + ps[tid + 256];
    float* x2p = x2 + (size_t)t * CH;
    x2p[tid] = v0; x2p[tid + 256] = v1;
    float s = v0 + v1, sq = v0 * v0 + v1 * v1;
    block_reduce_2(s, sq);
    float mu  = s * (1.0f / CH);
    float var = sq * (1.0f / CH) - mu * mu;
    float inv = rsqrtf(var + 1e-5f);
    size_t base = (size_t)t * CH;
    h2[base + tid]       = __float2half_rn((v0 - mu) * inv * g[tid]       + b[tid]);
    h2[base + tid + 256] = __float2half_rn((v1 - mu) * inv * g[tid + 256] + b[tid + 256]);
}

// ---------------- launcher ----------------
extern "C" void kernel_launch(void* const* d_in, const int* in_sizes, int n_in,
                              void* d_out, int out_size)
{
    const float* x          = (const float*)d_in[0];
    const float* w_qkv      = (const float*)d_in[3];
    const float* b_qkv      = (const float*)d_in[4];
    const float* w_proj     = (const float*)d_in[5];
    const float* b_proj     = (const float*)d_in[6];
    const float* bias_table = (const float*)d_in[7];
    const float* g1         = (const float*)d_in[8];
    const float* be1        = (const float*)d_in[9];
    const float* g2         = (const float*)d_in[10];
    const float* be2        = (const float*)d_in[11];
    const float* w1         = (const float*)d_in[12];
    const float* b1         = (const float*)d_in[13];
    const float* w2         = (const float*)d_in[14];
    const float* b2         = (const float*)d_in[15];
    float* out = (float*)d_out;

    half *p_xw, *p_qkv, *p_att, *p_h2, *p_ffn;
    float *p_proj, *p_x2;
    half *p_wqkv, *p_wproj, *p_w1, *p_w2;
    cudaGetSymbolAddress((void**)&p_xw,   g_xw);
    cudaGetSymbolAddress((void**)&p_qkv,  g_qkv);
    cudaGetSymbolAddress((void**)&p_att,  g_att);
    cudaGetSymbolAddress((void**)&p_proj, g_proj);
    cudaGetSymbolAddress((void**)&p_x2,   g_x2);
    cudaGetSymbolAddress((void**)&p_h2,   g_h2);
    cudaGetSymbolAddress((void**)&p_ffn,  g_ffn);
    cudaGetSymbolAddress((void**)&p_wqkv,  g_wqkv);
    cudaGetSymbolAddress((void**)&p_wproj, g_wproj);
    cudaGetSymbolAddress((void**)&p_w1,    g_w1);
    cudaGetSymbolAddress((void**)&p_w2,    g_w2);

    cudaFuncSetAttribute(hmma_gemm<0>, cudaFuncAttributeMaxDynamicSharedMemorySize, GSMEM);
    cudaFuncSetAttribute(hmma_gemm<1>, cudaFuncAttributeMaxDynamicSharedMemorySize, GSMEM);
    cudaFuncSetAttribute(hmma_gemm<2>, cudaFuncAttributeMaxDynamicSharedMemorySize, GSMEM);
    cudaFuncSetAttribute(hmma_gemm<3>, cudaFuncAttributeMaxDynamicSharedMemorySize, GSMEM);

    // weight prep (tiled transpose to fp16)
    prep_w<<<dim3((3*CH)/32, CH/32), 256>>>(w_qkv, p_wqkv, CH, 3*CH);
    prep_w<<<dim3(CH/32,     CH/32), 256>>>(w_proj, p_wproj, CH, CH);
    prep_w<<<dim3(CFF/32,    CH/32), 256>>>(w1, p_w1, CH, CFF);
    prep_w<<<dim3(CH/32,    CFF/32), 256>>>(w2, p_w2, CFF, CH);

    // 1. LN1 + shift + window partition -> fp16
    ln1_window_kernel<<<NTOK, 256>>>(x, g1, be1, p_xw);

    // 2. QKV GEMM -> fp16 (bias only)
    hmma_gemm<3><<<dim3((3*CH)/128, NTOK/128), 256, GSMEM>>>(
        p_xw, p_wqkv, b_qkv, nullptr, nullptr, p_qkv, CH, 3*CH);

    // 3. windowed attention -> fp16
    attn_kernel<<<NWIN * NHEAD, 128>>>(p_qkv, bias_table, p_att);

    // 4. proj GEMM -> fp32
    hmma_gemm<0><<<dim3(CH/128, NTOK/128), 256, GSMEM>>>(
        p_att, p_wproj, b_proj, nullptr, p_proj, nullptr, CH, CH);

    // 5. window reverse + roll + residual + LN2
    res_ln2_kernel<<<NTOK, 256>>>(x, p_proj, g2, be2, p_x2, p_h2);

    // 6. FFN1 + GELU -> fp16
    hmma_gemm<1><<<dim3(CFF/128, NTOK/128), 256, GSMEM>>>(
        p_h2, p_w1, b1, nullptr, nullptr, p_ffn, CH, CFF);

    // 7. FFN2 + residual -> out
    hmma_gemm<2><<<dim3(CH/128, NTOK/128), 256, GSMEM>>>(
        p_ffn, p_w2, b2, p_x2, out, nullptr, CFF, CH);
}

// round 8
// speedup vs baseline: 5.1626x; 1.2444x over previous
#include <cuda_runtime.h>
#include <cuda_fp16.h>
#include <math.h>
#include <stdint.h>

// ---------------- problem constants ----------------
#define BATCH 16
#define HDIM  56
#define WDIM  56
#define CH    512
#define CFF   2048
#define NHEAD 16
#define DH    32
#define MWIN  7
#define NTOKW 49
#define SHIFT 3
#define NTOK  (BATCH*HDIM*WDIM)                  // 50176
#define NWIN  (BATCH*(HDIM/MWIN)*(WDIM/MWIN))    // 1024

// ---------------- device scratch (allocation-free) ----------------
__device__ half  g_xw  [(size_t)NTOK*CH];
__device__ half  g_qkv [(size_t)NTOK*3*CH];
__device__ half  g_att [(size_t)NTOK*CH];
__device__ float g_proj[(size_t)NTOK*CH];
__device__ float g_x2  [(size_t)NTOK*CH];
__device__ half  g_h2  [(size_t)NTOK*CH];
__device__ half  g_ffn [(size_t)NTOK*CFF];
// weights transposed to [N,K] fp16
__device__ half g_wqkv [(size_t)CH*3*CH];
__device__ half g_wproj[(size_t)CH*CH];
__device__ half g_w1   [(size_t)CH*CFF];
__device__ half g_w2   [(size_t)CFF*CH];

// ---------------- PTX helpers ----------------
__device__ __forceinline__ uint32_t smem_u32(const void* p){
    uint32_t a;
    asm("{ .reg .u64 t; cvta.to.shared.u64 t, %1; cvt.u32.u64 %0, t; }" : "=r"(a) : "l"(p));
    return a;
}
#define CP_ASYNC16(dst, src) \
    asm volatile("cp.async.cg.shared.global [%0], [%1], 16;" :: "r"(dst), "l"(src))
#define CP_COMMIT() asm volatile("cp.async.commit_group;" ::: "memory")
#define CP_WAIT(N)  asm volatile("cp.async.wait_group %0;" :: "n"(N) : "memory")

#define LDSM_X4(r, a) \
    asm volatile("ldmatrix.sync.aligned.m8n8.x4.shared.b16 {%0,%1,%2,%3}, [%4];" \
        : "=r"((r)[0]), "=r"((r)[1]), "=r"((r)[2]), "=r"((r)[3]) : "r"(a))

#define MMA_F16(d, a, b0, b1) \
    asm volatile("mma.sync.aligned.m16n8k16.row.col.f32.f16.f16.f32 " \
        "{%0,%1,%2,%3}, {%4,%5,%6,%7}, {%8,%9}, {%0,%1,%2,%3};" \
        : "+f"((d)[0]), "+f"((d)[1]), "+f"((d)[2]), "+f"((d)[3]) \
        : "r"((a)[0]), "r"((a)[1]), "r"((a)[2]), "r"((a)[3]), "r"(b0), "r"(b1))

// ---------------- fp16 HMMA GEMM, 4-stage cp.async pipeline ----------------
#define TILEB  10240
#define STAGEB 20480
#define GSMEM  (4*STAGEB)

template<int EPI>
__global__ __launch_bounds__(256, 2) void hmma_gemm(
    const half* __restrict__ Ag, const half* __restrict__ Bg,
    const float* __restrict__ bias, const float* __restrict__ res,
    float* __restrict__ Cf, half* __restrict__ Ch,
    int K, int Nc)
{
    extern __shared__ char smem[];
    const int tid = threadIdx.x;
    const int lane = tid & 31, wid = tid >> 5;
    const int wm = wid & 1, wn = wid >> 1;          // warp tile: 64 x 32

    const half* Ab = Ag + (size_t)blockIdx.y * 128 * K;
    const half* Bb = Bg + (size_t)blockIdx.x * 128 * K;

    const uint32_t sb = smem_u32(smem);
    const int NK = K >> 5;

    float acc[4][4][4];
    #pragma unroll
    for (int a = 0; a < 4; a++)
        #pragma unroll
        for (int b = 0; b < 4; b++)
            #pragma unroll
            for (int c = 0; c < 4; c++) acc[a][b][c] = 0.f;

    const int lr0 = tid >> 2;          // 0..63
    const int lc  = tid & 3;           // 16B chunk 0..3
    auto load_stage = [&](int kb, int s) {
        uint32_t st = sb + (uint32_t)s * STAGEB;
        #pragma unroll
        for (int i = 0; i < 4; i++) {
            const int t = i >> 1;
            int r = (i & 1) * 64 + lr0;
            const half* src = (t ? Bb : Ab) + (size_t)r * K + kb * 32 + lc * 8;
            uint32_t dst = st + (uint32_t)(t * TILEB + r * 80 + lc * 16);
            CP_ASYNC16(dst, src);
        }
        CP_COMMIT();
    };

    auto compute_stage = [&](int s) {
        uint32_t st = sb + (uint32_t)s * STAGEB;
        #pragma unroll
        for (int kk = 0; kk < 2; kk++) {
            const int ch = kk * 2 + (lane >> 4);
            uint32_t bh[2][4];
            #pragma unroll
            for (int np = 0; np < 2; np++) {
                int row = wn * 32 + np * 16 + (lane & 15);
                uint32_t off = (uint32_t)(row * 80 + ch * 16);
                LDSM_X4(bh[np], st + 1u * TILEB + off);
            }
            #pragma unroll
            for (int mt = 0; mt < 4; mt++) {
                int row = wm * 64 + mt * 16 + (lane & 15);
                uint32_t off = (uint32_t)(row * 80 + ch * 16);
                uint32_t ah[4];
                LDSM_X4(ah, st + off);
                #pragma unroll
                for (int nt = 0; nt < 4; nt++) {
                    int np = nt >> 1, se = nt & 1;
                    MMA_F16(acc[mt][nt], ah, bh[np][se], bh[np][se + 2]);
                }
            }
        }
    };

    // prologue: fill 3 stages
    load_stage(0, 0);
    if (NK > 1) load_stage(1, 1);
    if (NK > 2) load_stage(2, 2);

    for (int kb = 0; kb < NK; kb++) {
        if (kb + 3 <= NK) { CP_WAIT(2); }
        else if (kb + 2 == NK) { CP_WAIT(1); }
        else { CP_WAIT(0); }
        __syncthreads();
        if (kb + 3 < NK) load_stage(kb + 3, (kb + 3) & 3);
        compute_stage(kb & 3);
    }

    // --- epilogue: registers -> gmem ---
    int row0 = blockIdx.y * 128 + wm * 64;
    int col0 = blockIdx.x * 128 + wn * 32;
    #pragma unroll
    for (int mt = 0; mt < 4; mt++) {
        #pragma unroll
        for (int nt = 0; nt < 4; nt++) {
            int c = col0 + nt * 8 + (lane & 3) * 2;
            float b0 = bias[c], b1 = bias[c + 1];
            #pragma unroll
            for (int h = 0; h < 2; h++) {
                int r = row0 + mt * 16 + (lane >> 2) + h * 8;
                float v0 = acc[mt][nt][h * 2]     + b0;
                float v1 = acc[mt][nt][h * 2 + 1] + b1;
                size_t o = (size_t)r * Nc + c;
                if (EPI == 1) {
                    v0 = 0.5f * v0 * (1.0f + erff(v0 * 0.70710678118654752f));
                    v1 = 0.5f * v1 * (1.0f + erff(v1 * 0.70710678118654752f));
                    *(half2*)(Ch + o) = __floats2half2_rn(v0, v1);
                } else if (EPI == 3) {
                    *(half2*)(Ch + o) = __floats2half2_rn(v0, v1);
                } else {
                    if (EPI == 2) {
                        float2 rv = *(const float2*)(res + o);
                        v0 += rv.x; v1 += rv.y;
                    }
                    *(float2*)(Cf + o) = make_float2(v0, v1);
                }
            }
        }
    }
}

// ---------------- weight prep: [K,N] fp32 -> [N,K] fp16 (tiled transpose) ----------------
__global__ __launch_bounds__(256) void prep_w(
    const float* __restrict__ W, half* __restrict__ Wh, int K, int N)
{
    __shared__ float tile[32][33];
    int nb = blockIdx.x * 32, kb = blockIdx.y * 32;
    int tx = threadIdx.x & 31, ty = threadIdx.x >> 5;  // 32 x 8
    #pragma unroll
    for (int j = 0; j < 32; j += 8)
        tile[ty + j][tx] = W[(size_t)(kb + ty + j) * N + nb + tx];
    __syncthreads();
    #pragma unroll
    for (int j = 0; j < 32; j += 8)
        Wh[(size_t)(nb + ty + j) * K + kb + tx] = __float2half_rn(tile[tx][ty + j]);
}

// ---------------- block reduction (256 threads) ----------------
__device__ __forceinline__ void block_reduce_2(float& s, float& sq) {
    __shared__ float sh[16];
    int lane = threadIdx.x & 31, wid = threadIdx.x >> 5;
    #pragma unroll
    for (int o = 16; o > 0; o >>= 1) {
        s  += __shfl_down_sync(0xffffffffu, s,  o);
        sq += __shfl_down_sync(0xffffffffu, sq, o);
    }
    if (lane == 0) { sh[wid] = s; sh[wid + 8] = sq; }
    __syncthreads();
    if (threadIdx.x == 0) {
        float S = 0.f, SQ = 0.f;
        #pragma unroll
        for (int i = 0; i < 8; i++) { S += sh[i]; SQ += sh[i + 8]; }
        sh[0] = S; sh[8] = SQ;
    }
    __syncthreads();
    s = sh[0]; sq = sh[8];
}

// ---------------- LN1 + shift + window partition -> fp16 ----------------
__global__ __launch_bounds__(256) void ln1_window_kernel(
    const float* __restrict__ x, const float* __restrict__ g, const float* __restrict__ b,
    half* __restrict__ out)
{
    int t = blockIdx.x;
    int w = t / NTOKW, tok = t - w * NTOKW;
    int bb = w >> 6, wrem = w & 63;
    int wi = wrem >> 3, wj = wrem & 7;
    int ti = tok / MWIN, tj = tok - ti * MWIN;
    int r = (wi * MWIN + ti + SHIFT) % HDIM;
    int c = (wj * MWIN + tj + SHIFT) % WDIM;
    const float* src = x + ((size_t)bb * (HDIM * WDIM) + r * WDIM + c) * CH;
    int tid = threadIdx.x;
    float v0 = src[tid], v1 = src[tid + 256];
    float s = v0 + v1, sq = v0 * v0 + v1 * v1;
    block_reduce_2(s, sq);
    float mu  = s * (1.0f / CH);
    float var = sq * (1.0f / CH) - mu * mu;
    float inv = rsqrtf(var + 1e-5f);
    size_t base = (size_t)t * CH;
    out[base + tid]       = __float2half_rn((v0 - mu) * inv * g[tid]       + b[tid]);
    out[base + tid + 256] = __float2half_rn((v1 - mu) * inv * g[tid + 256] + b[tid + 256]);
}

// ---------------- windowed attention: register-tiled ----------------
// One block (128 thr) per (window, head).
// smem rows: q/k/v stride 33 floats, scores stride 57 -> spread bank maps.
// QK^T: 13x7 grid of 4x7 per-thread tiles (91 threads); rows 49..51 compute
// garbage into never-read sc cells (no zero-fill needed; bias index clamped).
// AV: 13x8 grid of 4x4 tiles (104 threads); stores guarded to n<49.
__global__ __launch_bounds__(128) void attn_kernel(
    const half* __restrict__ qkv, const float* __restrict__ bias_table,
    half* __restrict__ out)
{
    int win  = blockIdx.x >> 4;
    int head = blockIdx.x & 15;
    __shared__ float q[52 * 33], kk[52 * 33], v[52 * 33];
    __shared__ float sc[52 * 57];
    int tid = threadIdx.x;
    const float scale = 0.17677669529663687f;
    size_t base = (size_t)win * NTOKW * (3 * CH) + head * DH;

    // load Q,K,V (half2 -> fp32 smem)
    for (int i = tid; i < NTOKW * 16; i += 128) {
        int n = i >> 4, d2 = (i & 15) * 2;
        size_t rb = base + (size_t)n * (3 * CH) + d2;
        float2 fq = __half22float2(*(const half2*)(qkv + rb));
        float2 fk = __half22float2(*(const half2*)(qkv + rb + CH));
        float2 fv = __half22float2(*(const half2*)(qkv + rb + 2 * CH));
        q [n * 33 + d2] = fq.x;  q [n * 33 + d2 + 1] = fq.y;
        kk[n * 33 + d2] = fk.x;  kk[n * 33 + d2 + 1] = fk.y;
        v [n * 33 + d2] = fv.x;  v [n * 33 + d2 + 1] = fv.y;
    }
    __syncthreads();

    // QK^T + bias
    if (tid < 91) {
        int tr = tid / 7, tc = tid - tr * 7;
        int n0 = tr * 4, m0 = tc * 7;
        float acc[4][7];
        #pragma unroll
        for (int i = 0; i < 4; i++)
            #pragma unroll
            for (int j = 0; j < 7; j++) acc[i][j] = 0.f;
        #pragma unroll 8
        for (int d = 0; d < DH; d++) {
            float qr[4], kr[7];
            #pragma unroll
            for (int i = 0; i < 4; i++) qr[i] = q[(n0 + i) * 33 + d];
            #pragma unroll
            for (int j = 0; j < 7; j++) kr[j] = kk[(m0 + j) * 33 + d];
            #pragma unroll
            for (int i = 0; i < 4; i++)
                #pragma unroll
                for (int j = 0; j < 7; j++)
                    acc[i][j] = fmaf(qr[i], kr[j], acc[i][j]);
        }
        #pragma unroll
        for (int i = 0; i < 4; i++) {
            int n = n0 + i;
            int nn = n < NTOKW ? n : NTOKW - 1;   // clamp for bias only
            int nr = nn / MWIN, ncm = nn - nr * MWIN;
            #pragma unroll
            for (int j = 0; j < 7; j++) {
                int m = m0 + j;
                int mr = m / MWIN, mc = m - mr * MWIN;
                int dr = nr - mr + (MWIN - 1), dc = ncm - mc + (MWIN - 1);
                sc[n * 57 + m] = acc[i][j] * scale
                               + bias_table[(dr * (2 * MWIN - 1) + dc) * NHEAD + head];
            }
        }
    }
    __syncthreads();

    // softmax per row
    if (tid < NTOKW) {
        float* row = sc + tid * 57;
        float mx = -1e30f;
        #pragma unroll 7
        for (int m = 0; m < NTOKW; m++) mx = fmaxf(mx, row[m]);
        float sum = 0.f;
        #pragma unroll 7
        for (int m = 0; m < NTOKW; m++) { float e = __expf(row[m] - mx); row[m] = e; sum += e; }
        float inv = 1.0f / sum;
        #pragma unroll 7
        for (int m = 0; m < NTOKW; m++) row[m] *= inv;
    }
    __syncthreads();

    // AV
    if (tid < 104) {
        int tr = tid >> 3, dc = tid & 7;
        int n0 = tr * 4, d0 = dc * 4;
        float acc[4][4];
        #pragma unroll
        for (int i = 0; i < 4; i++)
            #pragma unroll
            for (int k = 0; k < 4; k++) acc[i][k] = 0.f;
        #pragma unroll 7
        for (int m = 0; m < NTOKW; m++) {
            float vv[4], pp[4];
            #pragma unroll
            for (int k = 0; k < 4; k++) vv[k] = v[m * 33 + d0 + k];
            #pragma unroll
            for (int i = 0; i < 4; i++) pp[i] = sc[(n0 + i) * 57 + m];
            #pragma unroll
            for (int i = 0; i < 4; i++)
                #pragma unroll
                for (int k = 0; k < 4; k++)
                    acc[i][k] = fmaf(pp[i], vv[k], acc[i][k]);
        }
        #pragma unroll
        for (int i = 0; i < 4; i++) {
            int n = n0 + i;
            if (n < NTOKW) {
                size_t o = ((size_t)win * NTOKW + n) * CH + head * DH + d0;
                half2 h01 = __floats2half2_rn(acc[i][0], acc[i][1]);
                half2 h23 = __floats2half2_rn(acc[i][2], acc[i][3]);
                *(half2*)(out + o)     = h01;
                *(half2*)(out + o + 2) = h23;
            }
        }
    }
}

// ---------------- window reverse + roll + residual + LN2 ----------------
__global__ __launch_bounds__(256) void res_ln2_kernel(
    const float* __restrict__ x, const float* __restrict__ proj,
    const float* __restrict__ g, const float* __restrict__ b,
    float* __restrict__ x2, half* __restrict__ h2)
{
    int t = blockIdx.x;
    int bb = t / (HDIM * WDIM);
    int rc = t - bb * (HDIM * WDIM);
    int r = rc / WDIM, c = rc - r * WDIM;
    int rs = (r - SHIFT + HDIM) % HDIM;
    int cs = (c - SHIFT + WDIM) % WDIM;
    int w   = bb * 64 + (rs / MWIN) * 8 + (cs / MWIN);
    int tok = (rs % MWIN) * MWIN + (cs % MWIN);
    const float* ps = proj + ((size_t)w * NTOKW + tok) * CH;
    const float* xs = x + (size_t)t * CH;
    int tid = threadIdx.x;
    float v0 = xs[tid] + ps[tid];
    float v1 = xs[tid + 256] + ps[tid + 256];
    float* x2p = x2 + (size_t)t * CH;
    x2p[tid] = v0; x2p[tid + 256] = v1;
    float s = v0 + v1, sq = v0 * v0 + v1 * v1;
    block_reduce_2(s, sq);
    float mu  = s * (1.0f / CH);
    float var = sq * (1.0f / CH) - mu * mu;
    float inv = rsqrtf(var + 1e-5f);
    size_t base = (size_t)t * CH;
    h2[base + tid]       = __float2half_rn((v0 - mu) * inv * g[tid]       + b[tid]);
    h2[base + tid + 256] = __float2half_rn((v1 - mu) * inv * g[tid + 256] + b[tid + 256]);
}

// ---------------- launcher ----------------
extern "C" void kernel_launch(void* const* d_in, const int* in_sizes, int n_in,
                              void* d_out, int out_size)
{
    const float* x          = (const float*)d_in[0];
    const float* w_qkv      = (const float*)d_in[3];
    const float* b_qkv      = (const float*)d_in[4];
    const float* w_proj     = (const float*)d_in[5];
    const float* b_proj     = (const float*)d_in[6];
    const float* bias_table = (const float*)d_in[7];
    const float* g1         = (const float*)d_in[8];
    const float* be1        = (const float*)d_in[9];
    const float* g2         = (const float*)d_in[10];
    const float* be2        = (const float*)d_in[11];
    const float* w1         = (const float*)d_in[12];
    const float* b1         = (const float*)d_in[13];
    const float* w2         = (const float*)d_in[14];
    const float* b2         = (const float*)d_in[15];
    float* out = (float*)d_out;

    half *p_xw, *p_qkv, *p_att, *p_h2, *p_ffn;
    float *p_proj, *p_x2;
    half *p_wqkv, *p_wproj, *p_w1, *p_w2;
    cudaGetSymbolAddress((void**)&p_xw,   g_xw);
    cudaGetSymbolAddress((void**)&p_qkv,  g_qkv);
    cudaGetSymbolAddress((void**)&p_att,  g_att);
    cudaGetSymbolAddress((void**)&p_proj, g_proj);
    cudaGetSymbolAddress((void**)&p_x2,   g_x2);
    cudaGetSymbolAddress((void**)&p_h2,   g_h2);
    cudaGetSymbolAddress((void**)&p_ffn,  g_ffn);
    cudaGetSymbolAddress((void**)&p_wqkv,  g_wqkv);
    cudaGetSymbolAddress((void**)&p_wproj, g_wproj);
    cudaGetSymbolAddress((void**)&p_w1,    g_w1);
    cudaGetSymbolAddress((void**)&p_w2,    g_w2);

    cudaFuncSetAttribute(hmma_gemm<0>, cudaFuncAttributeMaxDynamicSharedMemorySize, GSMEM);
    cudaFuncSetAttribute(hmma_gemm<1>, cudaFuncAttributeMaxDynamicSharedMemorySize, GSMEM);
    cudaFuncSetAttribute(hmma_gemm<2>, cudaFuncAttributeMaxDynamicSharedMemorySize, GSMEM);
    cudaFuncSetAttribute(hmma_gemm<3>, cudaFuncAttributeMaxDynamicSharedMemorySize, GSMEM);

    // weight prep (tiled transpose to fp16)
    prep_w<<<dim3((3*CH)/32, CH/32), 256>>>(w_qkv, p_wqkv, CH, 3*CH);
    prep_w<<<dim3(CH/32,     CH/32), 256>>>(w_proj, p_wproj, CH, CH);
    prep_w<<<dim3(CFF/32,    CH/32), 256>>>(w1, p_w1, CH, CFF);
    prep_w<<<dim3(CH/32,    CFF/32), 256>>>(w2, p_w2, CFF, CH);

    // 1. LN1 + shift + window partition -> fp16
    ln1_window_kernel<<<NTOK, 256>>>(x, g1, be1, p_xw);

    // 2. QKV GEMM -> fp16 (bias only)
    hmma_gemm<3><<<dim3((3*CH)/128, NTOK/128), 256, GSMEM>>>(
        p_xw, p_wqkv, b_qkv, nullptr, nullptr, p_qkv, CH, 3*CH);

    // 3. windowed attention -> fp16
    attn_kernel<<<NWIN * NHEAD, 128>>>(p_qkv, bias_table, p_att);

    // 4. proj GEMM -> fp32
    hmma_gemm<0><<<dim3(CH/128, NTOK/128), 256, GSMEM>>>(
        p_att, p_wproj, b_proj, nullptr, p_proj, nullptr, CH, CH);

    // 5. window reverse + roll + residual + LN2
    res_ln2_kernel<<<NTOK, 256>>>(x, p_proj, g2, be2, p_x2, p_h2);

    // 6. FFN1 + GELU -> fp16
    hmma_gemm<1><<<dim3(CFF/128, NTOK/128), 256, GSMEM>>>(
        p_h2, p_w1, b1, nullptr, nullptr, p_ffn, CH, CFF);

    // 7. FFN2 + residual -> out
    hmma_gemm<2><<<dim3(CH/128, NTOK/128), 256, GSMEM>>>(
        p_ffn, p_w2, b2, p_x2, out, nullptr, CFF, CH);
}